// round 1
// baseline (speedup 1.0000x reference)
#include <cuda_runtime.h>
#include <cuda_bf16.h>
#include <math.h>

// Problem constants
#define B   8
#define LQ  2048
#define LKV 2048
#define D   128
#define DV  128

// ---------------------------------------------------------------------------
// Kernel 1: S = (Q @ K^T) * scale
// grid (LKV/64, LQ/64, B), block (16,16). Each thread computes 4x4 outputs.
// ---------------------------------------------------------------------------
__global__ __launch_bounds__(256) void qk_kernel(const float* __restrict__ Q,
                                                 const float* __restrict__ K,
                                                 float* __restrict__ S) {
    const int b = blockIdx.z;
    const int mBase = blockIdx.y * 64;
    const int nBase = blockIdx.x * 64;

    __shared__ float Qs[64][33];
    __shared__ float Ks[64][33];

    const float* Qb = Q + (size_t)b * LQ * D;
    const float* Kb = K + (size_t)b * LKV * D;

    const int tx = threadIdx.x;
    const int ty = threadIdx.y;
    const int tid = ty * 16 + tx;

    float acc[4][4];
#pragma unroll
    for (int i = 0; i < 4; i++)
#pragma unroll
        for (int j = 0; j < 4; j++) acc[i][j] = 0.0f;

    for (int k0 = 0; k0 < D; k0 += 32) {
        // Load 64x32 tiles of Q and K (each thread: 2 float4 per tile)
#pragma unroll
        for (int l = 0; l < 2; l++) {
            int idx = tid + l * 256;        // 0..511 float4 slots
            int row = idx >> 3;             // 8 float4 per 32-wide row
            int col = (idx & 7) * 4;
            float4 q4 = *(const float4*)&Qb[(size_t)(mBase + row) * D + k0 + col];
            Qs[row][col + 0] = q4.x; Qs[row][col + 1] = q4.y;
            Qs[row][col + 2] = q4.z; Qs[row][col + 3] = q4.w;
            float4 k4 = *(const float4*)&Kb[(size_t)(nBase + row) * D + k0 + col];
            Ks[row][col + 0] = k4.x; Ks[row][col + 1] = k4.y;
            Ks[row][col + 2] = k4.z; Ks[row][col + 3] = k4.w;
        }
        __syncthreads();

#pragma unroll
        for (int k = 0; k < 32; k++) {
            float a[4], bb[4];
#pragma unroll
            for (int i = 0; i < 4; i++) a[i]  = Qs[ty * 4 + i][k];
#pragma unroll
            for (int j = 0; j < 4; j++) bb[j] = Ks[tx * 4 + j][k];
#pragma unroll
            for (int i = 0; i < 4; i++)
#pragma unroll
                for (int j = 0; j < 4; j++)
                    acc[i][j] = fmaf(a[i], bb[j], acc[i][j]);
        }
        __syncthreads();
    }

    const float scale = rsqrtf((float)D);
    float* Sb = S + (size_t)b * LQ * LKV;
#pragma unroll
    for (int i = 0; i < 4; i++) {
        int m = mBase + ty * 4 + i;
#pragma unroll
        for (int j = 0; j < 4; j++) {
            int n = nBase + tx * 4 + j;
            Sb[(size_t)m * LKV + n] = acc[i][j] * scale;
        }
    }
}

// ---------------------------------------------------------------------------
// Kernel 2: in-place row softmax over LKV=2048. One block (256 thr) per row.
// ---------------------------------------------------------------------------
__device__ __forceinline__ float block_reduce_max(float v, float* sh) {
    const int lane = threadIdx.x & 31;
    const int warp = threadIdx.x >> 5;
#pragma unroll
    for (int o = 16; o > 0; o >>= 1)
        v = fmaxf(v, __shfl_xor_sync(0xffffffffu, v, o));
    if (lane == 0) sh[warp] = v;
    __syncthreads();
    if (warp == 0) {
        float w = (lane < 8) ? sh[lane] : -INFINITY;
#pragma unroll
        for (int o = 4; o > 0; o >>= 1)
            w = fmaxf(w, __shfl_xor_sync(0xffffffffu, w, o));
        if (lane == 0) sh[0] = w;
    }
    __syncthreads();
    float r = sh[0];
    __syncthreads();
    return r;
}

__device__ __forceinline__ float block_reduce_sum(float v, float* sh) {
    const int lane = threadIdx.x & 31;
    const int warp = threadIdx.x >> 5;
#pragma unroll
    for (int o = 16; o > 0; o >>= 1)
        v += __shfl_xor_sync(0xffffffffu, v, o);
    if (lane == 0) sh[warp] = v;
    __syncthreads();
    if (warp == 0) {
        float w = (lane < 8) ? sh[lane] : 0.0f;
#pragma unroll
        for (int o = 4; o > 0; o >>= 1)
            w += __shfl_xor_sync(0xffffffffu, w, o);
        if (lane == 0) sh[0] = w;
    }
    __syncthreads();
    float r = sh[0];
    __syncthreads();
    return r;
}

__global__ __launch_bounds__(256) void softmax_kernel(float* __restrict__ S) {
    __shared__ float sh[8];
    float* row = S + (size_t)blockIdx.x * LKV;
    const int t = threadIdx.x;

    // Each thread: 8 elements as 2 float4 (stride-256*4 between the two)
    float4 v0 = *(const float4*)&row[t * 4];
    float4 v1 = *(const float4*)&row[1024 + t * 4];

    float m = fmaxf(fmaxf(fmaxf(v0.x, v0.y), fmaxf(v0.z, v0.w)),
                    fmaxf(fmaxf(v1.x, v1.y), fmaxf(v1.z, v1.w)));
    m = block_reduce_max(m, sh);

    v0.x = __expf(v0.x - m); v0.y = __expf(v0.y - m);
    v0.z = __expf(v0.z - m); v0.w = __expf(v0.w - m);
    v1.x = __expf(v1.x - m); v1.y = __expf(v1.y - m);
    v1.z = __expf(v1.z - m); v1.w = __expf(v1.w - m);

    float s = (v0.x + v0.y + v0.z + v0.w) + (v1.x + v1.y + v1.z + v1.w);
    s = block_reduce_sum(s, sh);
    float inv = 1.0f / s;

    v0.x *= inv; v0.y *= inv; v0.z *= inv; v0.w *= inv;
    v1.x *= inv; v1.y *= inv; v1.z *= inv; v1.w *= inv;

    *(float4*)&row[t * 4] = v0;
    *(float4*)&row[1024 + t * 4] = v1;
}

// ---------------------------------------------------------------------------
// Kernel 3: C = W @ V    (W: 2048x2048, V: 2048x128 per batch)
// grid (1, LQ/64, B), block (16,16). Each thread computes 4 rows x 8 cols.
// ---------------------------------------------------------------------------
__global__ __launch_bounds__(256) void wv_kernel(const float* __restrict__ W,
                                                 const float* __restrict__ V,
                                                 float* __restrict__ C) {
    const int b = blockIdx.z;
    const int mBase = blockIdx.y * 64;

    __shared__ float Ws[64][33];
    __shared__ float Vs[32][128];

    const float* Wb = W + (size_t)b * LQ * LKV;
    const float* Vb = V + (size_t)b * LKV * DV;

    const int tx = threadIdx.x;   // col group: tx*8
    const int ty = threadIdx.y;   // row group: ty*4
    const int tid = ty * 16 + tx;

    float acc[4][8];
#pragma unroll
    for (int i = 0; i < 4; i++)
#pragma unroll
        for (int j = 0; j < 8; j++) acc[i][j] = 0.0f;

    for (int k0 = 0; k0 < LKV; k0 += 32) {
        // W tile: 64x32 = 512 float4 slots
#pragma unroll
        for (int l = 0; l < 2; l++) {
            int idx = tid + l * 256;
            int row = idx >> 3;
            int col = (idx & 7) * 4;
            float4 w4 = *(const float4*)&Wb[(size_t)(mBase + row) * LKV + k0 + col];
            Ws[row][col + 0] = w4.x; Ws[row][col + 1] = w4.y;
            Ws[row][col + 2] = w4.z; Ws[row][col + 3] = w4.w;
        }
        // V tile: 32x128 = 1024 float4 slots
#pragma unroll
        for (int l = 0; l < 4; l++) {
            int idx = tid + l * 256;
            int row = idx >> 5;             // 32 float4 per 128-wide row
            int col = (idx & 31) * 4;
            float4 v4 = *(const float4*)&Vb[(size_t)(k0 + row) * DV + col];
            Vs[row][col + 0] = v4.x; Vs[row][col + 1] = v4.y;
            Vs[row][col + 2] = v4.z; Vs[row][col + 3] = v4.w;
        }
        __syncthreads();

#pragma unroll 8
        for (int k = 0; k < 32; k++) {
            float a[4];
#pragma unroll
            for (int i = 0; i < 4; i++) a[i] = Ws[ty * 4 + i][k];
            float bb[8];
#pragma unroll
            for (int j = 0; j < 8; j++) bb[j] = Vs[k][tx * 8 + j];
#pragma unroll
            for (int i = 0; i < 4; i++)
#pragma unroll
                for (int j = 0; j < 8; j++)
                    acc[i][j] = fmaf(a[i], bb[j], acc[i][j]);
        }
        __syncthreads();
    }

    float* Cb = C + (size_t)b * LQ * DV;
#pragma unroll
    for (int i = 0; i < 4; i++) {
        int m = mBase + ty * 4 + i;
#pragma unroll
        for (int j = 0; j < 8; j += 4) {
            int n = tx * 8 + j;
            float4 o = make_float4(acc[i][j], acc[i][j + 1], acc[i][j + 2], acc[i][j + 3]);
            *(float4*)&Cb[(size_t)m * DV + n] = o;
        }
    }
}

// ---------------------------------------------------------------------------
extern "C" void kernel_launch(void* const* d_in, const int* in_sizes, int n_in,
                              void* d_out, int out_size) {
    const float* Q = (const float*)d_in[0];
    const float* K = (const float*)d_in[1];
    const float* V = (const float*)d_in[2];

    float* Wgt = (float*)d_out;                                   // weights (B,LQ,LKV)
    float* Ctx = (float*)d_out + (size_t)B * LQ * LKV;            // context (B,LQ,DV)

    dim3 g1(LKV / 64, LQ / 64, B);
    qk_kernel<<<g1, dim3(16, 16)>>>(Q, K, Wgt);

    softmax_kernel<<<B * LQ, 256>>>(Wgt);

    dim3 g3(1, LQ / 64, B);
    wv_kernel<<<g3, dim3(16, 16)>>>(Wgt, V, Ctx);
}

// round 3
// speedup vs baseline: 2.1999x; 2.1999x over previous
#include <cuda_runtime.h>
#include <cuda_bf16.h>
#include <math.h>
#include <stdint.h>

// Problem constants
#define B   8
#define LQ  2048
#define LKV 2048
#define D   128
#define DV  128

// ---------------------------------------------------------------------------
// Helpers: fp32 -> (hi,lo) bf16x2 split, and bf16 mma
// ---------------------------------------------------------------------------
// Packs (x0 -> low half, x1 -> high half). lo captures the fp32 residual.
__device__ __forceinline__ void cvt_split(float x0, float x1,
                                          uint32_t& hi, uint32_t& lo) {
    asm("cvt.rn.bf16x2.f32 %0, %1, %2;" : "=r"(hi) : "f"(x1), "f"(x0));
    float f0 = __uint_as_float(hi << 16);           // low bf16 -> fp32 (exact)
    float f1 = __uint_as_float(hi & 0xffff0000u);   // high bf16 -> fp32 (exact)
    asm("cvt.rn.bf16x2.f32 %0, %1, %2;" : "=r"(lo) : "f"(x1 - f1), "f"(x0 - f0));
}

__device__ __forceinline__ void mma16816(float* c,
                                         uint32_t a0, uint32_t a1, uint32_t a2, uint32_t a3,
                                         uint32_t b0, uint32_t b1) {
    asm volatile(
        "mma.sync.aligned.m16n8k16.row.col.f32.bf16.bf16.f32 "
        "{%0,%1,%2,%3}, {%4,%5,%6,%7}, {%8,%9}, {%0,%1,%2,%3};"
        : "+f"(c[0]), "+f"(c[1]), "+f"(c[2]), "+f"(c[3])
        : "r"(a0), "r"(a1), "r"(a2), "r"(a3), "r"(b0), "r"(b1));
}

// ---------------------------------------------------------------------------
// Kernel 1: S = (Q @ K^T) * scale, via split-bf16 tensor cores.
// Block tile 128x128, K chunked by 64. 8 warps, each 64x32 (4x4 m16n8 tiles).
// Smem u32 row stride 36 (32 k-pairs + 4 pad) -> conflict-free frag gathers.
// ---------------------------------------------------------------------------
#define QK_SROW 36

__global__ void __launch_bounds__(256, 2)
qk_mma_kernel(const float* __restrict__ Q, const float* __restrict__ K,
              float* __restrict__ S) {
    extern __shared__ uint32_t sm[];
    uint32_t* Qhi = sm;                       // 128*36
    uint32_t* Qlo = Qhi + 128 * QK_SROW;
    uint32_t* Khi = Qlo + 128 * QK_SROW;
    uint32_t* Klo = Khi + 128 * QK_SROW;

    const int b = blockIdx.z;
    const int mBase = blockIdx.y * 128;
    const int nBase = blockIdx.x * 128;
    const float* Qb = Q + (size_t)b * LQ * D;
    const float* Kb = K + (size_t)b * LKV * D;

    const int tid  = threadIdx.x;
    const int lane = tid & 31;
    const int warp = tid >> 5;
    const int g    = lane >> 2;
    const int tig  = lane & 3;
    const int wm   = warp >> 2;   // 0..1  -> 64 rows
    const int wn   = warp & 3;    // 0..3  -> 32 cols

    float acc[4][4][4];
#pragma unroll
    for (int mt = 0; mt < 4; mt++)
#pragma unroll
        for (int nt = 0; nt < 4; nt++)
#pragma unroll
            for (int i = 0; i < 4; i++) acc[mt][nt][i] = 0.0f;

    for (int k0 = 0; k0 < D; k0 += 64) {
        // ---- fill: 128 rows x 64 cols of Q and K, fp32 -> hi/lo bf16 ----
#pragma unroll
        for (int l = 0; l < 8; l++) {
            int idx = tid + l * 256;          // 0..2047
            int row = idx >> 4;               // 0..127
            int c4  = idx & 15;               // float4 index within 64 cols
            uint32_t h0, l0, h1, l1;
            float4 q4 = *(const float4*)&Qb[(size_t)(mBase + row) * D + k0 + c4 * 4];
            cvt_split(q4.x, q4.y, h0, l0);
            cvt_split(q4.z, q4.w, h1, l1);
            Qhi[row * QK_SROW + c4 * 2]     = h0;
            Qhi[row * QK_SROW + c4 * 2 + 1] = h1;
            Qlo[row * QK_SROW + c4 * 2]     = l0;
            Qlo[row * QK_SROW + c4 * 2 + 1] = l1;
            float4 k4 = *(const float4*)&Kb[(size_t)(nBase + row) * D + k0 + c4 * 4];
            cvt_split(k4.x, k4.y, h0, l0);
            cvt_split(k4.z, k4.w, h1, l1);
            Khi[row * QK_SROW + c4 * 2]     = h0;
            Khi[row * QK_SROW + c4 * 2 + 1] = h1;
            Klo[row * QK_SROW + c4 * 2]     = l0;
            Klo[row * QK_SROW + c4 * 2 + 1] = l1;
        }
        __syncthreads();

        // ---- compute: 4 k16 steps ----
#pragma unroll
        for (int ks = 0; ks < 4; ks++) {
            const int kp = ks * 8;
            uint32_t Ah[4][4], Al[4][4];
#pragma unroll
            for (int mt = 0; mt < 4; mt++) {
                int r0 = (wm * 64 + mt * 16 + g) * QK_SROW + kp + tig;
                int r1 = r0 + 8 * QK_SROW;
                Ah[mt][0] = Qhi[r0];     Ah[mt][1] = Qhi[r1];
                Ah[mt][2] = Qhi[r0 + 4]; Ah[mt][3] = Qhi[r1 + 4];
                Al[mt][0] = Qlo[r0];     Al[mt][1] = Qlo[r1];
                Al[mt][2] = Qlo[r0 + 4]; Al[mt][3] = Qlo[r1 + 4];
            }
#pragma unroll
            for (int nt = 0; nt < 4; nt++) {
                int rb = (wn * 32 + nt * 8 + g) * QK_SROW + kp + tig;
                uint32_t bh0 = Khi[rb], bh1 = Khi[rb + 4];
                uint32_t bl0 = Klo[rb], bl1 = Klo[rb + 4];
#pragma unroll
                for (int mt = 0; mt < 4; mt++) {
                    mma16816(acc[mt][nt], Ah[mt][0], Ah[mt][1], Ah[mt][2], Ah[mt][3], bh0, bh1);
                    mma16816(acc[mt][nt], Ah[mt][0], Ah[mt][1], Ah[mt][2], Ah[mt][3], bl0, bl1);
                    mma16816(acc[mt][nt], Al[mt][0], Al[mt][1], Al[mt][2], Al[mt][3], bh0, bh1);
                }
            }
        }
        __syncthreads();
    }

    const float scale = 0.08838834764831845f;  // 1/sqrt(128)
    float* Sb = S + (size_t)b * LQ * LKV + (size_t)mBase * LKV + nBase;
#pragma unroll
    for (int mt = 0; mt < 4; mt++) {
        int m0 = wm * 64 + mt * 16 + g;
#pragma unroll
        for (int nt = 0; nt < 4; nt++) {
            int n0 = wn * 32 + nt * 8 + tig * 2;
            float2 v0 = make_float2(acc[mt][nt][0] * scale, acc[mt][nt][1] * scale);
            float2 v1 = make_float2(acc[mt][nt][2] * scale, acc[mt][nt][3] * scale);
            *(float2*)&Sb[(size_t)m0 * LKV + n0]       = v0;
            *(float2*)&Sb[(size_t)(m0 + 8) * LKV + n0] = v1;
        }
    }
}

// ---------------------------------------------------------------------------
// Kernel 2: in-place row softmax over LKV=2048. One block (256 thr) per row.
// ---------------------------------------------------------------------------
__device__ __forceinline__ float block_reduce_max(float v, float* sh) {
    const int lane = threadIdx.x & 31;
    const int warp = threadIdx.x >> 5;
#pragma unroll
    for (int o = 16; o > 0; o >>= 1)
        v = fmaxf(v, __shfl_xor_sync(0xffffffffu, v, o));
    if (lane == 0) sh[warp] = v;
    __syncthreads();
    if (warp == 0) {
        float w = (lane < 8) ? sh[lane] : -INFINITY;
#pragma unroll
        for (int o = 4; o > 0; o >>= 1)
            w = fmaxf(w, __shfl_xor_sync(0xffffffffu, w, o));
        if (lane == 0) sh[0] = w;
    }
    __syncthreads();
    float r = sh[0];
    __syncthreads();
    return r;
}

__device__ __forceinline__ float block_reduce_sum(float v, float* sh) {
    const int lane = threadIdx.x & 31;
    const int warp = threadIdx.x >> 5;
#pragma unroll
    for (int o = 16; o > 0; o >>= 1)
        v += __shfl_xor_sync(0xffffffffu, v, o);
    if (lane == 0) sh[warp] = v;
    __syncthreads();
    if (warp == 0) {
        float w = (lane < 8) ? sh[lane] : 0.0f;
#pragma unroll
        for (int o = 4; o > 0; o >>= 1)
            w += __shfl_xor_sync(0xffffffffu, w, o);
        if (lane == 0) sh[0] = w;
    }
    __syncthreads();
    float r = sh[0];
    __syncthreads();
    return r;
}

__global__ __launch_bounds__(256) void softmax_kernel(float* __restrict__ S) {
    __shared__ float sh[8];
    float* row = S + (size_t)blockIdx.x * LKV;
    const int t = threadIdx.x;

    float4 v0 = *(const float4*)&row[t * 4];
    float4 v1 = *(const float4*)&row[1024 + t * 4];

    float m = fmaxf(fmaxf(fmaxf(v0.x, v0.y), fmaxf(v0.z, v0.w)),
                    fmaxf(fmaxf(v1.x, v1.y), fmaxf(v1.z, v1.w)));
    m = block_reduce_max(m, sh);

    v0.x = __expf(v0.x - m); v0.y = __expf(v0.y - m);
    v0.z = __expf(v0.z - m); v0.w = __expf(v0.w - m);
    v1.x = __expf(v1.x - m); v1.y = __expf(v1.y - m);
    v1.z = __expf(v1.z - m); v1.w = __expf(v1.w - m);

    float s = (v0.x + v0.y + v0.z + v0.w) + (v1.x + v1.y + v1.z + v1.w);
    s = block_reduce_sum(s, sh);
    float inv = 1.0f / s;

    v0.x *= inv; v0.y *= inv; v0.z *= inv; v0.w *= inv;
    v1.x *= inv; v1.y *= inv; v1.z *= inv; v1.w *= inv;

    *(float4*)&row[t * 4] = v0;
    *(float4*)&row[1024 + t * 4] = v1;
}

// ---------------------------------------------------------------------------
// Kernel 3: C = W @ V via split-bf16 tensor cores.
// Block tile 64(M) x 128(N=DV full), K chunked by 64. 8 warps, each 32x32.
// W smem stride 36 u32; V transposed into [n][kp] with stride 33 u32
// (fill stores conflict-free: lane -> n, addr stride 33 ≡ 1 mod 32).
// ---------------------------------------------------------------------------
#define WV_WROW 36
#define WV_VROW 33

__global__ void __launch_bounds__(256, 3)
wv_mma_kernel(const float* __restrict__ W, const float* __restrict__ V,
              float* __restrict__ C) {
    extern __shared__ uint32_t sm[];
    uint32_t* Whi = sm;                       // 64*36
    uint32_t* Wlo = Whi + 64 * WV_WROW;
    uint32_t* Vhi = Wlo + 64 * WV_WROW;       // 128*33
    uint32_t* Vlo = Vhi + 128 * WV_VROW;

    const int b = blockIdx.y;
    const int mBase = blockIdx.x * 64;
    const float* Wb = W + (size_t)b * LQ * LKV;
    const float* Vb = V + (size_t)b * LKV * DV;

    const int tid  = threadIdx.x;
    const int lane = tid & 31;
    const int warp = tid >> 5;
    const int g    = lane >> 2;
    const int tig  = lane & 3;
    const int wm   = warp >> 2;   // 0..1 -> 32 rows
    const int wn   = warp & 3;    // 0..3 -> 32 cols

    float acc[2][4][4];
#pragma unroll
    for (int mt = 0; mt < 2; mt++)
#pragma unroll
        for (int nt = 0; nt < 4; nt++)
#pragma unroll
            for (int i = 0; i < 4; i++) acc[mt][nt][i] = 0.0f;

    for (int k0 = 0; k0 < LKV; k0 += 64) {
        // ---- fill W: 64 rows x 64 cols ----
#pragma unroll
        for (int l = 0; l < 4; l++) {
            int idx = tid + l * 256;          // 0..1023
            int row = idx >> 4;               // 0..63
            int c4  = idx & 15;
            float4 w4 = *(const float4*)&Wb[(size_t)(mBase + row) * LKV + k0 + c4 * 4];
            uint32_t h0, l0, h1, l1;
            cvt_split(w4.x, w4.y, h0, l0);
            cvt_split(w4.z, w4.w, h1, l1);
            Whi[row * WV_WROW + c4 * 2]     = h0;
            Whi[row * WV_WROW + c4 * 2 + 1] = h1;
            Wlo[row * WV_WROW + c4 * 2]     = l0;
            Wlo[row * WV_WROW + c4 * 2 + 1] = l1;
        }
        // ---- fill V transposed: Vs[n][kp] = (V[k0+2kp][n], V[k0+2kp+1][n]) ----
#pragma unroll
        for (int l = 0; l < 16; l++) {
            int idx = tid + l * 256;          // 0..4095
            int n  = idx & 127;
            int kp = idx >> 7;                // 0..31
            float v0 = Vb[(size_t)(k0 + 2 * kp) * DV + n];
            float v1 = Vb[(size_t)(k0 + 2 * kp + 1) * DV + n];
            uint32_t h, lo;
            cvt_split(v0, v1, h, lo);
            Vhi[n * WV_VROW + kp] = h;
            Vlo[n * WV_VROW + kp] = lo;
        }
        __syncthreads();

        // ---- compute: 4 k16 steps ----
#pragma unroll
        for (int ks = 0; ks < 4; ks++) {
            const int kp = ks * 8;
            uint32_t Ah[2][4], Al[2][4];
#pragma unroll
            for (int mt = 0; mt < 2; mt++) {
                int r0 = (wm * 32 + mt * 16 + g) * WV_WROW + kp + tig;
                int r1 = r0 + 8 * WV_WROW;
                Ah[mt][0] = Whi[r0];     Ah[mt][1] = Whi[r1];
                Ah[mt][2] = Whi[r0 + 4]; Ah[mt][3] = Whi[r1 + 4];
                Al[mt][0] = Wlo[r0];     Al[mt][1] = Wlo[r1];
                Al[mt][2] = Wlo[r0 + 4]; Al[mt][3] = Wlo[r1 + 4];
            }
#pragma unroll
            for (int nt = 0; nt < 4; nt++) {
                int rb = (wn * 32 + nt * 8 + g) * WV_VROW + kp + tig;
                uint32_t bh0 = Vhi[rb], bh1 = Vhi[rb + 4];
                uint32_t bl0 = Vlo[rb], bl1 = Vlo[rb + 4];
#pragma unroll
                for (int mt = 0; mt < 2; mt++) {
                    mma16816(acc[mt][nt], Ah[mt][0], Ah[mt][1], Ah[mt][2], Ah[mt][3], bh0, bh1);
                    mma16816(acc[mt][nt], Ah[mt][0], Ah[mt][1], Ah[mt][2], Ah[mt][3], bl0, bl1);
                    mma16816(acc[mt][nt], Al[mt][0], Al[mt][1], Al[mt][2], Al[mt][3], bh0, bh1);
                }
            }
        }
        __syncthreads();
    }

    float* Cb = C + (size_t)b * LQ * DV + (size_t)mBase * DV;
#pragma unroll
    for (int mt = 0; mt < 2; mt++) {
        int m0 = wm * 32 + mt * 16 + g;
#pragma unroll
        for (int nt = 0; nt < 4; nt++) {
            int n0 = wn * 32 + nt * 8 + tig * 2;
            float2 v0 = make_float2(acc[mt][nt][0], acc[mt][nt][1]);
            float2 v1 = make_float2(acc[mt][nt][2], acc[mt][nt][3]);
            *(float2*)&Cb[(size_t)m0 * DV + n0]       = v0;
            *(float2*)&Cb[(size_t)(m0 + 8) * DV + n0] = v1;
        }
    }
}

// ---------------------------------------------------------------------------
extern "C" void kernel_launch(void* const* d_in, const int* in_sizes, int n_in,
                              void* d_out, int out_size) {
    const float* Q = (const float*)d_in[0];
    const float* K = (const float*)d_in[1];
    const float* V = (const float*)d_in[2];

    float* Wgt = (float*)d_out;                        // weights (B,LQ,LKV)
    float* Ctx = (float*)d_out + (size_t)B * LQ * LKV; // context (B,LQ,DV)

    const int qk_smem = (4 * 128 * QK_SROW) * 4;                       // 73728 B
    const int wv_smem = (2 * 64 * WV_WROW + 2 * 128 * WV_VROW) * 4;    // 52224 B
    cudaFuncSetAttribute(qk_mma_kernel, cudaFuncAttributeMaxDynamicSharedMemorySize, qk_smem);
    cudaFuncSetAttribute(wv_mma_kernel, cudaFuncAttributeMaxDynamicSharedMemorySize, wv_smem);

    dim3 g1(LKV / 128, LQ / 128, B);
    qk_mma_kernel<<<g1, 256, qk_smem>>>(Q, K, Wgt);

    softmax_kernel<<<B * LQ, 256>>>(Wgt);

    dim3 g3(LQ / 64, B);
    wv_mma_kernel<<<g3, 256, wv_smem>>>(Wgt, V, Ctx);
}

// round 4
// speedup vs baseline: 2.2817x; 1.0372x over previous
#include <cuda_runtime.h>
#include <cuda_bf16.h>
#include <math.h>
#include <stdint.h>

// Problem constants
#define B   8
#define LQ  2048
#define LKV 2048
#define D   128
#define DV  128

// Per-row partial exp-sums: [batch][n-block (16 of 128 cols)][row]
__device__ float g_partial[B][LKV / 128][LQ];   // 1 MB static scratch

// ---------------------------------------------------------------------------
// Helpers
// ---------------------------------------------------------------------------
__device__ __forceinline__ void cvt_split(float x0, float x1,
                                          uint32_t& hi, uint32_t& lo) {
    asm("cvt.rn.bf16x2.f32 %0, %1, %2;" : "=r"(hi) : "f"(x1), "f"(x0));
    float f0 = __uint_as_float(hi << 16);
    float f1 = __uint_as_float(hi & 0xffff0000u);
    asm("cvt.rn.bf16x2.f32 %0, %1, %2;" : "=r"(lo) : "f"(x1 - f1), "f"(x0 - f0));
}

__device__ __forceinline__ void mma16816(float* c,
                                         uint32_t a0, uint32_t a1, uint32_t a2, uint32_t a3,
                                         uint32_t b0, uint32_t b1) {
    asm volatile(
        "mma.sync.aligned.m16n8k16.row.col.f32.bf16.bf16.f32 "
        "{%0,%1,%2,%3}, {%4,%5,%6,%7}, {%8,%9}, {%0,%1,%2,%3};"
        : "+f"(c[0]), "+f"(c[1]), "+f"(c[2]), "+f"(c[3])
        : "r"(a0), "r"(a1), "r"(a2), "r"(a3), "r"(b0), "r"(b1));
}

__device__ __forceinline__ void ldsm_x4(uint32_t& r0, uint32_t& r1,
                                        uint32_t& r2, uint32_t& r3, uint32_t addr) {
    asm volatile("ldmatrix.sync.aligned.m8n8.x4.shared.b16 {%0,%1,%2,%3}, [%4];"
                 : "=r"(r0), "=r"(r1), "=r"(r2), "=r"(r3) : "r"(addr));
}

__device__ __forceinline__ void ldsm_x2(uint32_t& r0, uint32_t& r1, uint32_t addr) {
    asm volatile("ldmatrix.sync.aligned.m8n8.x2.shared.b16 {%0,%1}, [%2];"
                 : "=r"(r0), "=r"(r1) : "r"(addr));
}

// ---------------------------------------------------------------------------
// Kernel 1: S = (Q @ K^T) * scale  +  per-row partial exp-sums.
// Block tile 128x128, K chunked by 64. 8 warps, each 64x32 (4x4 m16n8 tiles).
// Fragment loads via ldmatrix. Smem u32 row stride 36 (conflict-free).
// ---------------------------------------------------------------------------
#define QK_SROW 36

__global__ void __launch_bounds__(256, 2)
qk_mma_kernel(const float* __restrict__ Q, const float* __restrict__ K,
              float* __restrict__ S) {
    extern __shared__ uint32_t sm[];
    uint32_t* Qhi = sm;                       // 128*36
    uint32_t* Qlo = Qhi + 128 * QK_SROW;
    uint32_t* Khi = Qlo + 128 * QK_SROW;
    uint32_t* Klo = Khi + 128 * QK_SROW;

    const int b = blockIdx.z;
    const int mBase = blockIdx.y * 128;
    const int nBase = blockIdx.x * 128;
    const float* Qb = Q + (size_t)b * LQ * D;
    const float* Kb = K + (size_t)b * LKV * D;

    const int tid  = threadIdx.x;
    const int lane = tid & 31;
    const int warp = tid >> 5;
    const int g    = lane >> 2;
    const int tig  = lane & 3;
    const int wm   = warp >> 2;   // 0..1  -> 64 rows
    const int wn   = warp & 3;    // 0..3  -> 32 cols

    // ldmatrix shared addresses (bytes)
    const uint32_t smemS = (uint32_t)__cvta_generic_to_shared(sm);
    const uint32_t qhiS = smemS;
    const uint32_t khiS = smemS + 2u * 128 * QK_SROW * 4;
    const uint32_t LO_OFF = 128u * QK_SROW * 4;
    const uint32_t aBase = ((wm * 64 + (lane & 7) + (lane & 8)) * QK_SROW
                            + ((lane >> 4) & 1) * 4) * 4;
    const uint32_t bBase = ((wn * 32 + (lane & 7)) * QK_SROW
                            + ((lane >> 3) & 1) * 4) * 4;

    float acc[4][4][4];
#pragma unroll
    for (int mt = 0; mt < 4; mt++)
#pragma unroll
        for (int nt = 0; nt < 4; nt++)
#pragma unroll
            for (int i = 0; i < 4; i++) acc[mt][nt][i] = 0.0f;

    for (int k0 = 0; k0 < D; k0 += 64) {
        // ---- fill: 128 rows x 64 cols of Q and K, fp32 -> hi/lo bf16 ----
#pragma unroll
        for (int l = 0; l < 8; l++) {
            int idx = tid + l * 256;          // 0..2047
            int row = idx >> 4;               // 0..127
            int c4  = idx & 15;               // float4 index within 64 cols
            uint32_t h0, l0, h1, l1;
            float4 q4 = *(const float4*)&Qb[(size_t)(mBase + row) * D + k0 + c4 * 4];
            cvt_split(q4.x, q4.y, h0, l0);
            cvt_split(q4.z, q4.w, h1, l1);
            Qhi[row * QK_SROW + c4 * 2]     = h0;
            Qhi[row * QK_SROW + c4 * 2 + 1] = h1;
            Qlo[row * QK_SROW + c4 * 2]     = l0;
            Qlo[row * QK_SROW + c4 * 2 + 1] = l1;
            float4 k4 = *(const float4*)&Kb[(size_t)(nBase + row) * D + k0 + c4 * 4];
            cvt_split(k4.x, k4.y, h0, l0);
            cvt_split(k4.z, k4.w, h1, l1);
            Khi[row * QK_SROW + c4 * 2]     = h0;
            Khi[row * QK_SROW + c4 * 2 + 1] = h1;
            Klo[row * QK_SROW + c4 * 2]     = l0;
            Klo[row * QK_SROW + c4 * 2 + 1] = l1;
        }
        __syncthreads();

        // ---- compute: 4 k16 steps ----
#pragma unroll
        for (int ks = 0; ks < 4; ks++) {
            uint32_t Ah[4][4], Al[4][4];
#pragma unroll
            for (int mt = 0; mt < 4; mt++) {
                uint32_t a = qhiS + aBase + (uint32_t)mt * (16 * QK_SROW * 4) + (uint32_t)ks * 32;
                ldsm_x4(Ah[mt][0], Ah[mt][1], Ah[mt][2], Ah[mt][3], a);
                ldsm_x4(Al[mt][0], Al[mt][1], Al[mt][2], Al[mt][3], a + LO_OFF);
            }
#pragma unroll
            for (int nt = 0; nt < 4; nt++) {
                uint32_t ba = khiS + bBase + (uint32_t)nt * (8 * QK_SROW * 4) + (uint32_t)ks * 32;
                uint32_t bh0, bh1, bl0, bl1;
                ldsm_x2(bh0, bh1, ba);
                ldsm_x2(bl0, bl1, ba + LO_OFF);
#pragma unroll
                for (int mt = 0; mt < 4; mt++) {
                    mma16816(acc[mt][nt], Ah[mt][0], Ah[mt][1], Ah[mt][2], Ah[mt][3], bh0, bh1);
                    mma16816(acc[mt][nt], Ah[mt][0], Ah[mt][1], Ah[mt][2], Ah[mt][3], bl0, bl1);
                    mma16816(acc[mt][nt], Al[mt][0], Al[mt][1], Al[mt][2], Al[mt][3], bh0, bh1);
                }
            }
        }
        __syncthreads();
    }

    const float scale = 0.08838834764831845f;  // 1/sqrt(128)
    float* Sb = S + (size_t)b * LQ * LKV + (size_t)mBase * LKV + nBase;
#pragma unroll
    for (int mt = 0; mt < 4; mt++) {
        int m0 = wm * 64 + mt * 16 + g;
#pragma unroll
        for (int nt = 0; nt < 4; nt++) {
            int n0 = wn * 32 + nt * 8 + tig * 2;
            float2 v0 = make_float2(acc[mt][nt][0] * scale, acc[mt][nt][1] * scale);
            float2 v1 = make_float2(acc[mt][nt][2] * scale, acc[mt][nt][3] * scale);
            *(float2*)&Sb[(size_t)m0 * LKV + n0]       = v0;
            *(float2*)&Sb[(size_t)(m0 + 8) * LKV + n0] = v1;
        }
    }

    // ---- epilogue: per-row partial sum of exp(s) over this block's 128 cols ----
    float* part = (float*)sm;                 // reuse smem: [4 warps-n][128 rows]
#pragma unroll
    for (int mt = 0; mt < 4; mt++) {
        float eA = 0.0f, eB = 0.0f;
#pragma unroll
        for (int nt = 0; nt < 4; nt++) {
            eA += __expf(acc[mt][nt][0] * scale) + __expf(acc[mt][nt][1] * scale);
            eB += __expf(acc[mt][nt][2] * scale) + __expf(acc[mt][nt][3] * scale);
        }
        eA += __shfl_xor_sync(0xffffffffu, eA, 1);
        eA += __shfl_xor_sync(0xffffffffu, eA, 2);
        eB += __shfl_xor_sync(0xffffffffu, eB, 1);
        eB += __shfl_xor_sync(0xffffffffu, eB, 2);
        if (tig == 0) {
            part[wn * 128 + wm * 64 + mt * 16 + g]     = eA;
            part[wn * 128 + wm * 64 + mt * 16 + g + 8] = eB;
        }
    }
    __syncthreads();
    if (tid < 128) {
        float s = part[tid] + part[128 + tid] + part[256 + tid] + part[384 + tid];
        g_partial[b][blockIdx.x][mBase + tid] = s;
    }
}

// ---------------------------------------------------------------------------
// Kernel 2 (fused): softmax-normalize + C = P @ V via split-bf16 tensor cores.
// Reads raw scores S, computes p = exp(s) * invsum, writes p back in place
// (the weights output) and accumulates C. Block tile 64(M) x 128(N=DV).
// ---------------------------------------------------------------------------
#define WV_WROW 36
#define WV_VROW 33

__global__ void __launch_bounds__(256, 3)
wv_fused_kernel(float* __restrict__ SW,       // in: scores, out: weights (in place)
                const float* __restrict__ V,
                float* __restrict__ C) {
    extern __shared__ uint32_t sm[];
    uint32_t* Whi = sm;                       // 64*36
    uint32_t* Wlo = Whi + 64 * WV_WROW;
    uint32_t* Vhi = Wlo + 64 * WV_WROW;       // 128*33
    uint32_t* Vlo = Vhi + 128 * WV_VROW;
    float*    invs = (float*)(Vlo + 128 * WV_VROW);   // 64 floats

    const int b = blockIdx.y;
    const int mBase = blockIdx.x * 64;
    float* Wb = SW + (size_t)b * LQ * LKV;
    const float* Vb = V + (size_t)b * LKV * DV;

    const int tid  = threadIdx.x;
    const int lane = tid & 31;
    const int warp = tid >> 5;
    const int g    = lane >> 2;
    const int tig  = lane & 3;
    const int wm   = warp >> 2;   // 0..1 -> 32 rows
    const int wn   = warp & 3;    // 0..3 -> 32 cols

    // ---- row inverse sums from partials ----
    if (tid < 64) {
        float s = 0.0f;
#pragma unroll
        for (int nb = 0; nb < LKV / 128; nb++) s += g_partial[b][nb][mBase + tid];
        invs[tid] = 1.0f / s;
    }
    __syncthreads();

    float acc[2][4][4];
#pragma unroll
    for (int mt = 0; mt < 2; mt++)
#pragma unroll
        for (int nt = 0; nt < 4; nt++)
#pragma unroll
            for (int i = 0; i < 4; i++) acc[mt][nt][i] = 0.0f;

    for (int k0 = 0; k0 < LKV; k0 += 64) {
        // ---- fill W: 64 rows x 64 cols, with on-the-fly softmax + writeback ----
#pragma unroll
        for (int l = 0; l < 4; l++) {
            int idx = tid + l * 256;          // 0..1023
            int row = idx >> 4;               // 0..63
            int c4  = idx & 15;
            float* gp = &Wb[(size_t)(mBase + row) * LKV + k0 + c4 * 4];
            float4 w4 = *(const float4*)gp;
            float inv = invs[row];
            w4.x = __expf(w4.x) * inv;
            w4.y = __expf(w4.y) * inv;
            w4.z = __expf(w4.z) * inv;
            w4.w = __expf(w4.w) * inv;
            *(float4*)gp = w4;                // weights output (in place)
            uint32_t h0, l0, h1, l1;
            cvt_split(w4.x, w4.y, h0, l0);
            cvt_split(w4.z, w4.w, h1, l1);
            Whi[row * WV_WROW + c4 * 2]     = h0;
            Whi[row * WV_WROW + c4 * 2 + 1] = h1;
            Wlo[row * WV_WROW + c4 * 2]     = l0;
            Wlo[row * WV_WROW + c4 * 2 + 1] = l1;
        }
        // ---- fill V transposed: Vs[n][kp] = (V[k0+2kp][n], V[k0+2kp+1][n]) ----
#pragma unroll
        for (int l = 0; l < 16; l++) {
            int idx = tid + l * 256;          // 0..4095
            int n  = idx & 127;
            int kp = idx >> 7;                // 0..31
            float v0 = Vb[(size_t)(k0 + 2 * kp) * DV + n];
            float v1 = Vb[(size_t)(k0 + 2 * kp + 1) * DV + n];
            uint32_t h, lo;
            cvt_split(v0, v1, h, lo);
            Vhi[n * WV_VROW + kp] = h;
            Vlo[n * WV_VROW + kp] = lo;
        }
        __syncthreads();

        // ---- compute: 4 k16 steps ----
#pragma unroll
        for (int ks = 0; ks < 4; ks++) {
            const int kp = ks * 8;
            uint32_t Ah[2][4], Al[2][4];
#pragma unroll
            for (int mt = 0; mt < 2; mt++) {
                int r0 = (wm * 32 + mt * 16 + g) * WV_WROW + kp + tig;
                int r1 = r0 + 8 * WV_WROW;
                Ah[mt][0] = Whi[r0];     Ah[mt][1] = Whi[r1];
                Ah[mt][2] = Whi[r0 + 4]; Ah[mt][3] = Whi[r1 + 4];
                Al[mt][0] = Wlo[r0];     Al[mt][1] = Wlo[r1];
                Al[mt][2] = Wlo[r0 + 4]; Al[mt][3] = Wlo[r1 + 4];
            }
#pragma unroll
            for (int nt = 0; nt < 4; nt++) {
                int rb = (wn * 32 + nt * 8 + g) * WV_VROW + kp + tig;
                uint32_t bh0 = Vhi[rb], bh1 = Vhi[rb + 4];
                uint32_t bl0 = Vlo[rb], bl1 = Vlo[rb + 4];
#pragma unroll
                for (int mt = 0; mt < 2; mt++) {
                    mma16816(acc[mt][nt], Ah[mt][0], Ah[mt][1], Ah[mt][2], Ah[mt][3], bh0, bh1);
                    mma16816(acc[mt][nt], Ah[mt][0], Ah[mt][1], Ah[mt][2], Ah[mt][3], bl0, bl1);
                    mma16816(acc[mt][nt], Al[mt][0], Al[mt][1], Al[mt][2], Al[mt][3], bh0, bh1);
                }
            }
        }
        __syncthreads();
    }

    float* Cb = C + (size_t)b * LQ * DV + (size_t)mBase * DV;
#pragma unroll
    for (int mt = 0; mt < 2; mt++) {
        int m0 = wm * 32 + mt * 16 + g;
#pragma unroll
        for (int nt = 0; nt < 4; nt++) {
            int n0 = wn * 32 + nt * 8 + tig * 2;
            float2 v0 = make_float2(acc[mt][nt][0], acc[mt][nt][1]);
            float2 v1 = make_float2(acc[mt][nt][2], acc[mt][nt][3]);
            *(float2*)&Cb[(size_t)m0 * DV + n0]       = v0;
            *(float2*)&Cb[(size_t)(m0 + 8) * DV + n0] = v1;
        }
    }
}

// ---------------------------------------------------------------------------
extern "C" void kernel_launch(void* const* d_in, const int* in_sizes, int n_in,
                              void* d_out, int out_size) {
    const float* Q = (const float*)d_in[0];
    const float* K = (const float*)d_in[1];
    const float* V = (const float*)d_in[2];

    float* Wgt = (float*)d_out;                        // weights (B,LQ,LKV)
    float* Ctx = (float*)d_out + (size_t)B * LQ * LKV; // context (B,LQ,DV)

    const int qk_smem = (4 * 128 * QK_SROW) * 4;                             // 73728 B
    const int wv_smem = (2 * 64 * WV_WROW + 2 * 128 * WV_VROW) * 4 + 256;    // 52480 B
    cudaFuncSetAttribute(qk_mma_kernel, cudaFuncAttributeMaxDynamicSharedMemorySize, qk_smem);
    cudaFuncSetAttribute(wv_fused_kernel, cudaFuncAttributeMaxDynamicSharedMemorySize, wv_smem);

    dim3 g1(LKV / 128, LQ / 128, B);
    qk_mma_kernel<<<g1, 256, qk_smem>>>(Q, K, Wgt);

    dim3 g2(LQ / 64, B);
    wv_fused_kernel<<<g2, 256, wv_smem>>>(Wgt, V, Ctx);
}

// round 7
// speedup vs baseline: 2.4459x; 1.0720x over previous
#include <cuda_runtime.h>
#include <cuda_bf16.h>
#include <math.h>
#include <stdint.h>

// Problem constants
#define B   8
#define LQ  2048
#define LKV 2048
#define D   128
#define DV  128
#define KSPLIT 4
#define KRANGE (LKV / KSPLIT)   // 512

// Per-row partial exp-sums: [batch][n-block (16 of 128 cols)][row]
__device__ float g_partial[B][LKV / 128][LQ];            // 1 MB
// Split-K partial context: [split][batch][row][dv]
__device__ float g_partC[KSPLIT][B][LQ][DV];             // 32 MB

// ---------------------------------------------------------------------------
// Helpers
// ---------------------------------------------------------------------------
__device__ __forceinline__ void cvt_split(float x0, float x1,
                                          uint32_t& hi, uint32_t& lo) {
    asm("cvt.rn.bf16x2.f32 %0, %1, %2;" : "=r"(hi) : "f"(x1), "f"(x0));
    float f0 = __uint_as_float(hi << 16);
    float f1 = __uint_as_float(hi & 0xffff0000u);
    asm("cvt.rn.bf16x2.f32 %0, %1, %2;" : "=r"(lo) : "f"(x1 - f1), "f"(x0 - f0));
}

__device__ __forceinline__ void mma16816(float* c,
                                         uint32_t a0, uint32_t a1, uint32_t a2, uint32_t a3,
                                         uint32_t b0, uint32_t b1) {
    asm volatile(
        "mma.sync.aligned.m16n8k16.row.col.f32.bf16.bf16.f32 "
        "{%0,%1,%2,%3}, {%4,%5,%6,%7}, {%8,%9}, {%0,%1,%2,%3};"
        : "+f"(c[0]), "+f"(c[1]), "+f"(c[2]), "+f"(c[3])
        : "r"(a0), "r"(a1), "r"(a2), "r"(a3), "r"(b0), "r"(b1));
}

__device__ __forceinline__ void ldsm_x4(uint32_t& r0, uint32_t& r1,
                                        uint32_t& r2, uint32_t& r3, uint32_t addr) {
    asm volatile("ldmatrix.sync.aligned.m8n8.x4.shared.b16 {%0,%1,%2,%3}, [%4];"
                 : "=r"(r0), "=r"(r1), "=r"(r2), "=r"(r3) : "r"(addr));
}

__device__ __forceinline__ void ldsm_x2(uint32_t& r0, uint32_t& r1, uint32_t addr) {
    asm volatile("ldmatrix.sync.aligned.m8n8.x2.shared.b16 {%0,%1}, [%2];"
                 : "=r"(r0), "=r"(r1) : "r"(addr));
}

// ---------------------------------------------------------------------------
// Kernel 1: S = (Q @ K^T) * scale  +  per-row partial exp-sums.
// Block tile 128x128, K chunked by 64. 8 warps, each 64x32 (4x4 m16n8 tiles).
// ---------------------------------------------------------------------------
#define QK_SROW 36

__global__ void __launch_bounds__(256, 2)
qk_mma_kernel(const float* __restrict__ Q, const float* __restrict__ K,
              float* __restrict__ S) {
    extern __shared__ uint32_t sm[];
    uint32_t* Qhi = sm;                       // 128*36
    uint32_t* Qlo = Qhi + 128 * QK_SROW;
    uint32_t* Khi = Qlo + 128 * QK_SROW;
    uint32_t* Klo = Khi + 128 * QK_SROW;

    const int b = blockIdx.z;
    const int mBase = blockIdx.y * 128;
    const int nBase = blockIdx.x * 128;
    const float* Qb = Q + (size_t)b * LQ * D;
    const float* Kb = K + (size_t)b * LKV * D;

    const int tid  = threadIdx.x;
    const int lane = tid & 31;
    const int warp = tid >> 5;
    const int g    = lane >> 2;
    const int tig  = lane & 3;
    const int wm   = warp >> 2;   // 0..1  -> 64 rows
    const int wn   = warp & 3;    // 0..3  -> 32 cols

    const uint32_t smemS = (uint32_t)__cvta_generic_to_shared(sm);
    const uint32_t qhiS = smemS;
    const uint32_t khiS = smemS + 2u * 128 * QK_SROW * 4;
    const uint32_t LO_OFF = 128u * QK_SROW * 4;
    const uint32_t aBase = ((wm * 64 + (lane & 7) + (lane & 8)) * QK_SROW
                            + ((lane >> 4) & 1) * 4) * 4;
    const uint32_t bBase = ((wn * 32 + (lane & 7)) * QK_SROW
                            + ((lane >> 3) & 1) * 4) * 4;

    float acc[4][4][4];
#pragma unroll
    for (int mt = 0; mt < 4; mt++)
#pragma unroll
        for (int nt = 0; nt < 4; nt++)
#pragma unroll
            for (int i = 0; i < 4; i++) acc[mt][nt][i] = 0.0f;

    for (int k0 = 0; k0 < D; k0 += 64) {
#pragma unroll
        for (int l = 0; l < 8; l++) {
            int idx = tid + l * 256;
            int row = idx >> 4;
            int c4  = idx & 15;
            uint32_t h0, l0, h1, l1;
            float4 q4 = *(const float4*)&Qb[(size_t)(mBase + row) * D + k0 + c4 * 4];
            cvt_split(q4.x, q4.y, h0, l0);
            cvt_split(q4.z, q4.w, h1, l1);
            Qhi[row * QK_SROW + c4 * 2]     = h0;
            Qhi[row * QK_SROW + c4 * 2 + 1] = h1;
            Qlo[row * QK_SROW + c4 * 2]     = l0;
            Qlo[row * QK_SROW + c4 * 2 + 1] = l1;
            float4 k4 = *(const float4*)&Kb[(size_t)(nBase + row) * D + k0 + c4 * 4];
            cvt_split(k4.x, k4.y, h0, l0);
            cvt_split(k4.z, k4.w, h1, l1);
            Khi[row * QK_SROW + c4 * 2]     = h0;
            Khi[row * QK_SROW + c4 * 2 + 1] = h1;
            Klo[row * QK_SROW + c4 * 2]     = l0;
            Klo[row * QK_SROW + c4 * 2 + 1] = l1;
        }
        __syncthreads();

#pragma unroll
        for (int ks = 0; ks < 4; ks++) {
            uint32_t Ah[4][4], Al[4][4];
#pragma unroll
            for (int mt = 0; mt < 4; mt++) {
                uint32_t a = qhiS + aBase + (uint32_t)mt * (16 * QK_SROW * 4) + (uint32_t)ks * 32;
                ldsm_x4(Ah[mt][0], Ah[mt][1], Ah[mt][2], Ah[mt][3], a);
                ldsm_x4(Al[mt][0], Al[mt][1], Al[mt][2], Al[mt][3], a + LO_OFF);
            }
#pragma unroll
            for (int nt = 0; nt < 4; nt++) {
                uint32_t ba = khiS + bBase + (uint32_t)nt * (8 * QK_SROW * 4) + (uint32_t)ks * 32;
                uint32_t bh0, bh1, bl0, bl1;
                ldsm_x2(bh0, bh1, ba);
                ldsm_x2(bl0, bl1, ba + LO_OFF);
#pragma unroll
                for (int mt = 0; mt < 4; mt++) {
                    mma16816(acc[mt][nt], Ah[mt][0], Ah[mt][1], Ah[mt][2], Ah[mt][3], bh0, bh1);
                    mma16816(acc[mt][nt], Ah[mt][0], Ah[mt][1], Ah[mt][2], Ah[mt][3], bl0, bl1);
                    mma16816(acc[mt][nt], Al[mt][0], Al[mt][1], Al[mt][2], Al[mt][3], bh0, bh1);
                }
            }
        }
        __syncthreads();
    }

    const float scale = 0.08838834764831845f;  // 1/sqrt(128)
    float* Sb = S + (size_t)b * LQ * LKV + (size_t)mBase * LKV + nBase;
#pragma unroll
    for (int mt = 0; mt < 4; mt++) {
        int m0 = wm * 64 + mt * 16 + g;
#pragma unroll
        for (int nt = 0; nt < 4; nt++) {
            int n0 = wn * 32 + nt * 8 + tig * 2;
            float2 v0 = make_float2(acc[mt][nt][0] * scale, acc[mt][nt][1] * scale);
            float2 v1 = make_float2(acc[mt][nt][2] * scale, acc[mt][nt][3] * scale);
            *(float2*)&Sb[(size_t)m0 * LKV + n0]       = v0;
            *(float2*)&Sb[(size_t)(m0 + 8) * LKV + n0] = v1;
        }
    }

    // ---- epilogue: per-row partial sum of exp(s) over this block's 128 cols ----
    float* part = (float*)sm;                 // reuse smem: [4 warps-n][128 rows]
#pragma unroll
    for (int mt = 0; mt < 4; mt++) {
        float eA = 0.0f, eB = 0.0f;
#pragma unroll
        for (int nt = 0; nt < 4; nt++) {
            eA += __expf(acc[mt][nt][0] * scale) + __expf(acc[mt][nt][1] * scale);
            eB += __expf(acc[mt][nt][2] * scale) + __expf(acc[mt][nt][3] * scale);
        }
        eA += __shfl_xor_sync(0xffffffffu, eA, 1);
        eA += __shfl_xor_sync(0xffffffffu, eA, 2);
        eB += __shfl_xor_sync(0xffffffffu, eB, 1);
        eB += __shfl_xor_sync(0xffffffffu, eB, 2);
        if (tig == 0) {
            part[wn * 128 + wm * 64 + mt * 16 + g]     = eA;
            part[wn * 128 + wm * 64 + mt * 16 + g + 8] = eB;
        }
    }
    __syncthreads();
    if (tid < 128) {
        float s = part[tid] + part[128 + tid] + part[256 + tid] + part[384 + tid];
        g_partial[b][blockIdx.x][mBase + tid] = s;
    }
}

// ---------------------------------------------------------------------------
// Kernel 2 (fused, split-K): softmax-normalize + partial C = P @ V.
// Block tile 64(M) x 128(N=DV), K range 512 (blockIdx.y selects split).
// W A-fragments via ldmatrix (stride-36 layout, 16B-aligned rows).
// ---------------------------------------------------------------------------
#define WV_WROW 36
#define WV_VROW 33

__global__ void __launch_bounds__(256, 3)
wv_fused_kernel(float* __restrict__ SW,       // in: scores, out: weights (in place)
                const float* __restrict__ V) {
    extern __shared__ uint32_t sm[];
    uint32_t* Whi = sm;                       // 64*36
    uint32_t* Wlo = Whi + 64 * WV_WROW;
    uint32_t* Vhi = Wlo + 64 * WV_WROW;       // 128*33
    uint32_t* Vlo = Vhi + 128 * WV_VROW;
    float*    invs = (float*)(Vlo + 128 * WV_VROW);   // 64 floats

    const int b = blockIdx.z;
    const int ksp = blockIdx.y;
    const int mBase = blockIdx.x * 64;
    const int kBase = ksp * KRANGE;
    float* Wb = SW + (size_t)b * LQ * LKV;
    const float* Vb = V + (size_t)b * LKV * DV;

    const int tid  = threadIdx.x;
    const int lane = tid & 31;
    const int warp = tid >> 5;
    const int g    = lane >> 2;
    const int tig  = lane & 3;
    const int wm   = warp >> 2;   // 0..1 -> 32 rows
    const int wn   = warp & 3;    // 0..3 -> 32 cols

    // ldmatrix addresses for W (A-side)
    const uint32_t whiS = (uint32_t)__cvta_generic_to_shared(sm);
    const uint32_t LO_OFF_W = 64u * WV_WROW * 4;
    const uint32_t aBase = ((wm * 32 + (lane & 7) + (lane & 8)) * WV_WROW
                            + ((lane >> 4) & 1) * 4) * 4;

    // ---- row inverse sums from partials ----
    if (tid < 64) {
        float s = 0.0f;
#pragma unroll
        for (int nb = 0; nb < LKV / 128; nb++) s += g_partial[b][nb][mBase + tid];
        invs[tid] = 1.0f / s;
    }
    __syncthreads();

    float acc[2][4][4];
#pragma unroll
    for (int mt = 0; mt < 2; mt++)
#pragma unroll
        for (int nt = 0; nt < 4; nt++)
#pragma unroll
            for (int i = 0; i < 4; i++) acc[mt][nt][i] = 0.0f;

    for (int kc = 0; kc < KRANGE; kc += 64) {
        const int k0 = kBase + kc;
        // ---- fill W: 64 rows x 64 cols, with on-the-fly softmax + writeback ----
#pragma unroll
        for (int l = 0; l < 4; l++) {
            int idx = tid + l * 256;
            int row = idx >> 4;
            int c4  = idx & 15;
            float* gp = &Wb[(size_t)(mBase + row) * LKV + k0 + c4 * 4];
            float4 w4 = *(const float4*)gp;
            float inv = invs[row];
            w4.x = __expf(w4.x) * inv;
            w4.y = __expf(w4.y) * inv;
            w4.z = __expf(w4.z) * inv;
            w4.w = __expf(w4.w) * inv;
            *(float4*)gp = w4;                // weights output (in place)
            uint32_t h0, l0, h1, l1;
            cvt_split(w4.x, w4.y, h0, l0);
            cvt_split(w4.z, w4.w, h1, l1);
            Whi[row * WV_WROW + c4 * 2]     = h0;
            Whi[row * WV_WROW + c4 * 2 + 1] = h1;
            Wlo[row * WV_WROW + c4 * 2]     = l0;
            Wlo[row * WV_WROW + c4 * 2 + 1] = l1;
        }
        // ---- fill V transposed: Vs[n][kp] ----
#pragma unroll
        for (int l = 0; l < 16; l++) {
            int idx = tid + l * 256;
            int n  = idx & 127;
            int kp = idx >> 7;
            float v0 = Vb[(size_t)(k0 + 2 * kp) * DV + n];
            float v1 = Vb[(size_t)(k0 + 2 * kp + 1) * DV + n];
            uint32_t h, lo;
            cvt_split(v0, v1, h, lo);
            Vhi[n * WV_VROW + kp] = h;
            Vlo[n * WV_VROW + kp] = lo;
        }
        __syncthreads();

#pragma unroll
        for (int ks = 0; ks < 4; ks++) {
            const int kp = ks * 8;
            uint32_t Ah[2][4], Al[2][4];
#pragma unroll
            for (int mt = 0; mt < 2; mt++) {
                uint32_t a = whiS + aBase + (uint32_t)mt * (16 * WV_WROW * 4) + (uint32_t)ks * 32;
                ldsm_x4(Ah[mt][0], Ah[mt][1], Ah[mt][2], Ah[mt][3], a);
                ldsm_x4(Al[mt][0], Al[mt][1], Al[mt][2], Al[mt][3], a + LO_OFF_W);
            }
#pragma unroll
            for (int nt = 0; nt < 4; nt++) {
                int rb = (wn * 32 + nt * 8 + g) * WV_VROW + kp + tig;
                uint32_t bh0 = Vhi[rb], bh1 = Vhi[rb + 4];
                uint32_t bl0 = Vlo[rb], bl1 = Vlo[rb + 4];
#pragma unroll
                for (int mt = 0; mt < 2; mt++) {
                    mma16816(acc[mt][nt], Ah[mt][0], Ah[mt][1], Ah[mt][2], Ah[mt][3], bh0, bh1);
                    mma16816(acc[mt][nt], Ah[mt][0], Ah[mt][1], Ah[mt][2], Ah[mt][3], bl0, bl1);
                    mma16816(acc[mt][nt], Al[mt][0], Al[mt][1], Al[mt][2], Al[mt][3], bh0, bh1);
                }
            }
        }
        __syncthreads();
    }

    float* Cp = &g_partC[ksp][b][mBase][0];
#pragma unroll
    for (int mt = 0; mt < 2; mt++) {
        int m0 = wm * 32 + mt * 16 + g;
#pragma unroll
        for (int nt = 0; nt < 4; nt++) {
            int n0 = wn * 32 + nt * 8 + tig * 2;
            float2 v0 = make_float2(acc[mt][nt][0], acc[mt][nt][1]);
            float2 v1 = make_float2(acc[mt][nt][2], acc[mt][nt][3]);
            *(float2*)&Cp[(size_t)m0 * DV + n0]       = v0;
            *(float2*)&Cp[(size_t)(m0 + 8) * DV + n0] = v1;
        }
    }
}

// ---------------------------------------------------------------------------
// Kernel 3: reduce the KSPLIT partial C buffers into the context output.
// ---------------------------------------------------------------------------
__global__ void __launch_bounds__(256) reduce_kernel(float* __restrict__ C) {
    size_t i4 = (size_t)blockIdx.x * 256 + threadIdx.x;   // float4 index
    const float4* p0 = (const float4*)&g_partC[0][0][0][0];
    const float4* p1 = (const float4*)&g_partC[1][0][0][0];
    const float4* p2 = (const float4*)&g_partC[2][0][0][0];
    const float4* p3 = (const float4*)&g_partC[3][0][0][0];
    float4 a = p0[i4], b4 = p1[i4], c = p2[i4], d = p3[i4];
    float4 o;
    o.x = (a.x + b4.x) + (c.x + d.x);
    o.y = (a.y + b4.y) + (c.y + d.y);
    o.z = (a.z + b4.z) + (c.z + d.z);
    o.w = (a.w + b4.w) + (c.w + d.w);
    ((float4*)C)[i4] = o;
}

// ---------------------------------------------------------------------------
extern "C" void kernel_launch(void* const* d_in, const int* in_sizes, int n_in,
                              void* d_out, int out_size) {
    const float* Q = (const float*)d_in[0];
    const float* K = (const float*)d_in[1];
    const float* V = (const float*)d_in[2];

    float* Wgt = (float*)d_out;                        // weights (B,LQ,LKV)
    float* Ctx = (float*)d_out + (size_t)B * LQ * LKV; // context (B,LQ,DV)

    const int qk_smem = (4 * 128 * QK_SROW) * 4;                             // 73728 B
    const int wv_smem = (2 * 64 * WV_WROW + 2 * 128 * WV_VROW) * 4 + 256;    // 52480 B
    cudaFuncSetAttribute(qk_mma_kernel, cudaFuncAttributeMaxDynamicSharedMemorySize, qk_smem);
    cudaFuncSetAttribute(wv_fused_kernel, cudaFuncAttributeMaxDynamicSharedMemorySize, wv_smem);

    dim3 g1(LKV / 128, LQ / 128, B);
    qk_mma_kernel<<<g1, 256, qk_smem>>>(Q, K, Wgt);

    dim3 g2(LQ / 64, KSPLIT, B);
    wv_fused_kernel<<<g2, 256, wv_smem>>>(Wgt, V);

    const int nC4 = B * LQ * DV / 4;                   // 524288 float4
    reduce_kernel<<<nC4 / 256, 256>>>(Ctx);
}

// round 11
// speedup vs baseline: 2.8640x; 1.1710x over previous
#include <cuda_runtime.h>
#include <cuda_bf16.h>
#include <math.h>
#include <stdint.h>

// Problem constants
#define B   8
#define LQ  2048
#define LKV 2048
#define D   128
#define DV  128
#define KSPLIT 4
#define KRANGE (LKV / KSPLIT)   // 512

// ---------------------------------------------------------------------------
// Device scratch (static: no allocation allowed)
// ---------------------------------------------------------------------------
__device__ uint32_t g_Qhi[B][LQ][D / 2];          // 4 MB each
__device__ uint32_t g_Qlo[B][LQ][D / 2];
__device__ uint32_t g_Khi[B][LKV][D / 2];
__device__ uint32_t g_Klo[B][LKV][D / 2];
__device__ uint32_t g_Vthi[B][DV][LKV / 2];       // 4 MB each (V transposed)
__device__ uint32_t g_Vtlo[B][DV][LKV / 2];
__device__ uint32_t g_Ehi[B][LQ][LKV / 2];        // 64 MB each: exp(s) split
__device__ uint32_t g_Elo[B][LQ][LKV / 2];
__device__ float    g_partial[B][LKV / 128][LQ];  // per-row partial exp sums
__device__ float    g_partC[KSPLIT][B][LQ][DV];   // split-K partial context

// ---------------------------------------------------------------------------
// Helpers
// ---------------------------------------------------------------------------
__device__ __forceinline__ void cvt_split(float x0, float x1,
                                          uint32_t& hi, uint32_t& lo) {
    asm("cvt.rn.bf16x2.f32 %0, %1, %2;" : "=r"(hi) : "f"(x1), "f"(x0));
    float f0 = __uint_as_float(hi << 16);
    float f1 = __uint_as_float(hi & 0xffff0000u);
    asm("cvt.rn.bf16x2.f32 %0, %1, %2;" : "=r"(lo) : "f"(x1 - f1), "f"(x0 - f0));
}

__device__ __forceinline__ void mma16816(float* c,
                                         uint32_t a0, uint32_t a1, uint32_t a2, uint32_t a3,
                                         uint32_t b0, uint32_t b1) {
    asm volatile(
        "mma.sync.aligned.m16n8k16.row.col.f32.bf16.bf16.f32 "
        "{%0,%1,%2,%3}, {%4,%5,%6,%7}, {%8,%9}, {%0,%1,%2,%3};"
        : "+f"(c[0]), "+f"(c[1]), "+f"(c[2]), "+f"(c[3])
        : "r"(a0), "r"(a1), "r"(a2), "r"(a3), "r"(b0), "r"(b1));
}

__device__ __forceinline__ void ldsm_x4(uint32_t& r0, uint32_t& r1,
                                        uint32_t& r2, uint32_t& r3, uint32_t addr) {
    asm volatile("ldmatrix.sync.aligned.m8n8.x4.shared.b16 {%0,%1,%2,%3}, [%4];"
                 : "=r"(r0), "=r"(r1), "=r"(r2), "=r"(r3) : "r"(addr));
}

__device__ __forceinline__ void ldsm_x2(uint32_t& r0, uint32_t& r1, uint32_t addr) {
    asm volatile("ldmatrix.sync.aligned.m8n8.x2.shared.b16 {%0,%1}, [%2];"
                 : "=r"(r0), "=r"(r1) : "r"(addr));
}

__device__ __forceinline__ void cp16(uint32_t dst, const void* src) {
    asm volatile("cp.async.cg.shared.global [%0], [%1], 16;" :: "r"(dst), "l"(src));
}
#define CP_COMMIT() asm volatile("cp.async.commit_group;" ::: "memory")
#define CP_WAIT()   asm volatile("cp.async.wait_group 0;" ::: "memory")

// ---------------------------------------------------------------------------
// Convert kernels: fp32 -> split bf16 planes
// ---------------------------------------------------------------------------
__global__ void __launch_bounds__(256)
convert_qk_kernel(const float* __restrict__ Q, const float* __restrict__ K) {
    int idx = blockIdx.x * 256 + threadIdx.x;      // float4 index, 0..524287
    const float4* src = (const float4*)(blockIdx.y ? K : Q);
    uint2* dhi = (uint2*)(blockIdx.y ? &g_Khi[0][0][0] : &g_Qhi[0][0][0]);
    uint2* dlo = (uint2*)(blockIdx.y ? &g_Klo[0][0][0] : &g_Qlo[0][0][0]);
    float4 v = src[idx];
    uint32_t h0, l0, h1, l1;
    cvt_split(v.x, v.y, h0, l0);
    cvt_split(v.z, v.w, h1, l1);
    dhi[idx] = make_uint2(h0, h1);
    dlo[idx] = make_uint2(l0, l1);
}

__global__ void __launch_bounds__(256)
convert_v_kernel(const float* __restrict__ V) {
    __shared__ float Vs[32][132];
    const int b  = blockIdx.y;
    const int k0 = blockIdx.x * 32;
    const int tid = threadIdx.x;
#pragma unroll
    for (int l = 0; l < 4; l++) {
        int idx = tid + l * 256;          // 0..1023 float4 slots (32x128)
        int r  = idx >> 5;
        int c4 = idx & 31;
        float4 v = *(const float4*)&V[((size_t)(b * LKV + k0 + r)) * DV + c4 * 4];
        Vs[r][c4 * 4 + 0] = v.x; Vs[r][c4 * 4 + 1] = v.y;
        Vs[r][c4 * 4 + 2] = v.z; Vs[r][c4 * 4 + 3] = v.w;
    }
    __syncthreads();
#pragma unroll
    for (int l = 0; l < 8; l++) {
        int idx = tid + l * 256;          // 0..2047
        int n   = idx >> 4;               // 0..127
        int kpl = idx & 15;               // 0..15
        float v0 = Vs[2 * kpl][n];
        float v1 = Vs[2 * kpl + 1][n];
        uint32_t h, lo;
        cvt_split(v0, v1, h, lo);
        g_Vthi[b][n][k0 / 2 + kpl] = h;
        g_Vtlo[b][n][k0 / 2 + kpl] = lo;
    }
}

// ---------------------------------------------------------------------------
// Kernel 1: scores -> exp(s) split planes + per-row partial exp-sums.
// Block tile 128x128, K chunked by 64. cp.async fills from pre-split planes.
// ---------------------------------------------------------------------------
#define QK_SROW 36

__global__ void __launch_bounds__(256, 2)
qk_mma_kernel() {
    extern __shared__ uint32_t sm[];
    const uint32_t smemS = (uint32_t)__cvta_generic_to_shared(sm);
    const uint32_t LO_OFF = 128u * QK_SROW * 4;     // 18432 B
    const uint32_t KHI_OFF = 2u * LO_OFF;           // 36864 B

    const int b = blockIdx.z;
    const int mBase = blockIdx.y * 128;
    const int nBase = blockIdx.x * 128;

    const int tid  = threadIdx.x;
    const int lane = tid & 31;
    const int warp = tid >> 5;
    const int g    = lane >> 2;
    const int tig  = lane & 3;
    const int wm   = warp >> 2;   // 0..1  -> 64 rows
    const int wn   = warp & 3;    // 0..3  -> 32 cols

    const uint32_t aBase = ((wm * 64 + (lane & 7) + (lane & 8)) * QK_SROW
                            + ((lane >> 4) & 1) * 4) * 4;
    const uint32_t bBase = ((wn * 32 + (lane & 7)) * QK_SROW
                            + ((lane >> 3) & 1) * 4) * 4;

    float acc[4][4][4];
#pragma unroll
    for (int mt = 0; mt < 4; mt++)
#pragma unroll
        for (int nt = 0; nt < 4; nt++)
#pragma unroll
            for (int i = 0; i < 4; i++) acc[mt][nt][i] = 0.0f;

#pragma unroll
    for (int i = 0; i < 2; i++) {
        // ---- cp.async fill: 4 planes, 128 rows x 32 u32 each ----
#pragma unroll
        for (int l = 0; l < 4; l++) {
            int idx = tid + l * 256;      // 0..1023
            int row = idx >> 3;
            int c   = idx & 7;
            uint32_t d = smemS + row * 144 + c * 16;
            cp16(d,                    &g_Qhi[b][mBase + row][i * 32 + c * 4]);
            cp16(d + LO_OFF,           &g_Qlo[b][mBase + row][i * 32 + c * 4]);
            cp16(d + KHI_OFF,          &g_Khi[b][nBase + row][i * 32 + c * 4]);
            cp16(d + KHI_OFF + LO_OFF, &g_Klo[b][nBase + row][i * 32 + c * 4]);
        }
        CP_COMMIT();
        CP_WAIT();
        __syncthreads();

#pragma unroll
        for (int ks = 0; ks < 4; ks++) {
            uint32_t Ah[4][4], Al[4][4];
#pragma unroll
            for (int mt = 0; mt < 4; mt++) {
                uint32_t a = smemS + aBase + (uint32_t)mt * (16 * QK_SROW * 4) + (uint32_t)ks * 32;
                ldsm_x4(Ah[mt][0], Ah[mt][1], Ah[mt][2], Ah[mt][3], a);
                ldsm_x4(Al[mt][0], Al[mt][1], Al[mt][2], Al[mt][3], a + LO_OFF);
            }
#pragma unroll
            for (int nt = 0; nt < 4; nt++) {
                uint32_t ba = smemS + KHI_OFF + bBase + (uint32_t)nt * (8 * QK_SROW * 4) + (uint32_t)ks * 32;
                uint32_t bh0, bh1, bl0, bl1;
                ldsm_x2(bh0, bh1, ba);
                ldsm_x2(bl0, bl1, ba + LO_OFF);
#pragma unroll
                for (int mt = 0; mt < 4; mt++) {
                    mma16816(acc[mt][nt], Ah[mt][0], Ah[mt][1], Ah[mt][2], Ah[mt][3], bh0, bh1);
                    mma16816(acc[mt][nt], Ah[mt][0], Ah[mt][1], Ah[mt][2], Ah[mt][3], bl0, bl1);
                    mma16816(acc[mt][nt], Al[mt][0], Al[mt][1], Al[mt][2], Al[mt][3], bh0, bh1);
                }
            }
        }
        __syncthreads();
    }

    // ---- epilogue: e = exp(s*scale); write split E planes + partial sums ----
    const float scale = 0.08838834764831845f;  // 1/sqrt(128)
    float* part = (float*)sm;
#pragma unroll
    for (int mt = 0; mt < 4; mt++) {
        int m0 = mBase + wm * 64 + mt * 16 + g;
        float eA = 0.0f, eB = 0.0f;
#pragma unroll
        for (int nt = 0; nt < 4; nt++) {
            int kp = (nBase >> 1) + wn * 16 + nt * 4 + tig;
            float e0 = __expf(acc[mt][nt][0] * scale);
            float e1 = __expf(acc[mt][nt][1] * scale);
            float e2 = __expf(acc[mt][nt][2] * scale);
            float e3 = __expf(acc[mt][nt][3] * scale);
            uint32_t h, lo;
            cvt_split(e0, e1, h, lo);
            g_Ehi[b][m0][kp] = h;
            g_Elo[b][m0][kp] = lo;
            cvt_split(e2, e3, h, lo);
            g_Ehi[b][m0 + 8][kp] = h;
            g_Elo[b][m0 + 8][kp] = lo;
            eA += e0 + e1;
            eB += e2 + e3;
        }
        eA += __shfl_xor_sync(0xffffffffu, eA, 1);
        eA += __shfl_xor_sync(0xffffffffu, eA, 2);
        eB += __shfl_xor_sync(0xffffffffu, eB, 1);
        eB += __shfl_xor_sync(0xffffffffu, eB, 2);
        if (tig == 0) {
            part[wn * 128 + wm * 64 + mt * 16 + g]     = eA;
            part[wn * 128 + wm * 64 + mt * 16 + g + 8] = eB;
        }
    }
    __syncthreads();
    if (tid < 128) {
        float s = part[tid] + part[128 + tid] + part[256 + tid] + part[384 + tid];
        g_partial[b][blockIdx.x][mBase + tid] = s;
    }
}

// ---------------------------------------------------------------------------
// Kernel 2 (fused, split-K): weights output + partial C = E @ V (scaled by inv).
// Block tile 64(M) x 128(N=DV), K range 512. cp.async fills; ldmatrix A frags.
// ---------------------------------------------------------------------------
#define WV_ROW 36

__global__ void __launch_bounds__(256, 3)
wv_fused_kernel(float* __restrict__ Wgt) {
    extern __shared__ uint32_t sm[];
    uint32_t* Vhi = sm + 4608;                 // 128*36
    uint32_t* Vlo = sm + 9216;
    float*    invs = (float*)(sm + 13824);     // 64 floats
    const uint32_t smemS = (uint32_t)__cvta_generic_to_shared(sm);
    const uint32_t WLO_OFF = 9216;             // bytes (64*36*4)
    const uint32_t VHI_OFF = 18432;
    const uint32_t VLO_OFF = 36864;

    const int b = blockIdx.z;
    const int ksp = blockIdx.y;
    const int mBase = blockIdx.x * 64;
    const int kBase = ksp * KRANGE;

    const int tid  = threadIdx.x;
    const int lane = tid & 31;
    const int warp = tid >> 5;
    const int g    = lane >> 2;
    const int tig  = lane & 3;
    const int wm   = warp >> 2;   // 0..1 -> 32 rows
    const int wn   = warp & 3;    // 0..3 -> 32 cols

    const uint32_t aBase = ((wm * 32 + (lane & 7) + (lane & 8)) * WV_ROW
                            + ((lane >> 4) & 1) * 4) * 4;

    // ---- row inverse sums from partials ----
    if (tid < 64) {
        float s = 0.0f;
#pragma unroll
        for (int nb = 0; nb < LKV / 128; nb++) s += g_partial[b][nb][mBase + tid];
        invs[tid] = 1.0f / s;
    }
    __syncthreads();

    float acc[2][4][4];
#pragma unroll
    for (int mt = 0; mt < 2; mt++)
#pragma unroll
        for (int nt = 0; nt < 4; nt++)
#pragma unroll
            for (int i = 0; i < 4; i++) acc[mt][nt][i] = 0.0f;

    for (int kc = 0; kc < KRANGE; kc += 64) {
        const int k0 = kBase + kc;
        const int kp0 = k0 >> 1;
        // ---- cp.async fill: W(E) 64x32 u32, V 128x32 u32, hi+lo ----
#pragma unroll
        for (int l = 0; l < 2; l++) {
            int idx = tid + l * 256;      // 0..511
            int row = idx >> 3;
            int c   = idx & 7;
            uint32_t d = smemS + row * 144 + c * 16;
            cp16(d,           &g_Ehi[b][mBase + row][kp0 + c * 4]);
            cp16(d + WLO_OFF, &g_Elo[b][mBase + row][kp0 + c * 4]);
        }
#pragma unroll
        for (int l = 0; l < 4; l++) {
            int idx = tid + l * 256;      // 0..1023
            int n = idx >> 3;
            int c = idx & 7;
            uint32_t d = smemS + n * 144 + c * 16;
            cp16(d + VHI_OFF, &g_Vthi[b][n][kp0 + c * 4]);
            cp16(d + VLO_OFF, &g_Vtlo[b][n][kp0 + c * 4]);
        }
        CP_COMMIT();
        CP_WAIT();
        __syncthreads();

        // ---- weights output: P = (Ehi + Elo) * inv ----
#pragma unroll
        for (int l = 0; l < 4; l++) {
            int idx = tid + l * 256;      // 0..1023
            int row = idx >> 4;           // 0..63
            int c4  = idx & 15;           // float4 within 64 k-elems
            uint2 h  = *(uint2*)&sm[row * WV_ROW + c4 * 2];
            uint2 lo = *(uint2*)&sm[2304 + row * WV_ROW + c4 * 2];
            float inv = invs[row];
            float4 o;
            o.x = (__uint_as_float(h.x << 16)         + __uint_as_float(lo.x << 16))         * inv;
            o.y = (__uint_as_float(h.x & 0xffff0000u) + __uint_as_float(lo.x & 0xffff0000u)) * inv;
            o.z = (__uint_as_float(h.y << 16)         + __uint_as_float(lo.y << 16))         * inv;
            o.w = (__uint_as_float(h.y & 0xffff0000u) + __uint_as_float(lo.y & 0xffff0000u)) * inv;
            *(float4*)&Wgt[(size_t)(b) * LQ * LKV + (size_t)(mBase + row) * LKV + k0 + c4 * 4] = o;
        }

        // ---- mma: 4 k16 steps ----
#pragma unroll
        for (int ks = 0; ks < 4; ks++) {
            const int kp = ks * 8;
            uint32_t Ah[2][4], Al[2][4];
#pragma unroll
            for (int mt = 0; mt < 2; mt++) {
                uint32_t a = smemS + aBase + (uint32_t)mt * (16 * WV_ROW * 4) + (uint32_t)ks * 32;
                ldsm_x4(Ah[mt][0], Ah[mt][1], Ah[mt][2], Ah[mt][3], a);
                ldsm_x4(Al[mt][0], Al[mt][1], Al[mt][2], Al[mt][3], a + WLO_OFF);
            }
#pragma unroll
            for (int nt = 0; nt < 4; nt++) {
                int rb = (wn * 32 + nt * 8 + g) * WV_ROW + kp + tig;
                uint32_t bh0 = Vhi[rb], bh1 = Vhi[rb + 4];
                uint32_t bl0 = Vlo[rb], bl1 = Vlo[rb + 4];
#pragma unroll
                for (int mt = 0; mt < 2; mt++) {
                    mma16816(acc[mt][nt], Ah[mt][0], Ah[mt][1], Ah[mt][2], Ah[mt][3], bh0, bh1);
                    mma16816(acc[mt][nt], Ah[mt][0], Ah[mt][1], Ah[mt][2], Ah[mt][3], bl0, bl1);
                    mma16816(acc[mt][nt], Al[mt][0], Al[mt][1], Al[mt][2], Al[mt][3], bh0, bh1);
                }
            }
        }
        __syncthreads();
    }

    float* Cp = &g_partC[ksp][b][mBase][0];
#pragma unroll
    for (int mt = 0; mt < 2; mt++) {
        int r = wm * 32 + mt * 16 + g;
        float ia = invs[r];
        float ib = invs[r + 8];
#pragma unroll
        for (int nt = 0; nt < 4; nt++) {
            int n0 = wn * 32 + nt * 8 + tig * 2;
            float2 v0 = make_float2(acc[mt][nt][0] * ia, acc[mt][nt][1] * ia);
            float2 v1 = make_float2(acc[mt][nt][2] * ib, acc[mt][nt][3] * ib);
            *(float2*)&Cp[(size_t)r * DV + n0]       = v0;
            *(float2*)&Cp[(size_t)(r + 8) * DV + n0] = v1;
        }
    }
}

// ---------------------------------------------------------------------------
// Kernel 3: reduce the KSPLIT partial C buffers into the context output.
// ---------------------------------------------------------------------------
__global__ void __launch_bounds__(256) reduce_kernel(float* __restrict__ C) {
    size_t i4 = (size_t)blockIdx.x * 256 + threadIdx.x;   // float4 index
    const float4* p0 = (const float4*)&g_partC[0][0][0][0];
    const float4* p1 = (const float4*)&g_partC[1][0][0][0];
    const float4* p2 = (const float4*)&g_partC[2][0][0][0];
    const float4* p3 = (const float4*)&g_partC[3][0][0][0];
    float4 a = p0[i4], b4 = p1[i4], c = p2[i4], d = p3[i4];
    float4 o;
    o.x = (a.x + b4.x) + (c.x + d.x);
    o.y = (a.y + b4.y) + (c.y + d.y);
    o.z = (a.z + b4.z) + (c.z + d.z);
    o.w = (a.w + b4.w) + (c.w + d.w);
    ((float4*)C)[i4] = o;
}

// ---------------------------------------------------------------------------
extern "C" void kernel_launch(void* const* d_in, const int* in_sizes, int n_in,
                              void* d_out, int out_size) {
    const float* Q = (const float*)d_in[0];
    const float* K = (const float*)d_in[1];
    const float* V = (const float*)d_in[2];

    float* Wgt = (float*)d_out;                        // weights (B,LQ,LKV)
    float* Ctx = (float*)d_out + (size_t)B * LQ * LKV; // context (B,LQ,DV)

    const int qk_smem = 4 * 128 * QK_SROW * 4;                           // 73728 B
    const int wv_smem = (2 * 64 * WV_ROW + 2 * 128 * WV_ROW) * 4 + 256;  // 55552 B
    cudaFuncSetAttribute(qk_mma_kernel, cudaFuncAttributeMaxDynamicSharedMemorySize, qk_smem);
    cudaFuncSetAttribute(wv_fused_kernel, cudaFuncAttributeMaxDynamicSharedMemorySize, wv_smem);

    // Pre-convert inputs to split-bf16 planes
    dim3 gc(B * LQ * D / 4 / 256, 2);
    convert_qk_kernel<<<gc, 256>>>(Q, K);
    dim3 gv(LKV / 32, B);
    convert_v_kernel<<<gv, 256>>>(V);

    dim3 g1(LKV / 128, LQ / 128, B);
    qk_mma_kernel<<<g1, 256, qk_smem>>>();

    dim3 g2(LQ / 64, KSPLIT, B);
    wv_fused_kernel<<<g2, 256, wv_smem>>>(Wgt);

    const int nC4 = B * LQ * DV / 4;                   // 524288 float4
    reduce_kernel<<<nC4 / 256, 256>>>(Ctx);
}

// round 14
// speedup vs baseline: 2.9364x; 1.0253x over previous
#include <cuda_runtime.h>
#include <cuda_bf16.h>
#include <math.h>
#include <stdint.h>

// Problem constants
#define B   8
#define LQ  2048
#define LKV 2048
#define D   128
#define DV  128
#define KSPLIT 4
#define KRANGE (LKV / KSPLIT)   // 512

// ---------------------------------------------------------------------------
// Device scratch (static: no allocation allowed)
// ---------------------------------------------------------------------------
__device__ uint32_t g_Qhi[B][LQ][D / 2];
__device__ uint32_t g_Qlo[B][LQ][D / 2];
__device__ uint32_t g_Khi[B][LKV][D / 2];
__device__ uint32_t g_Klo[B][LKV][D / 2];
__device__ uint32_t g_Vthi[B][DV][LKV / 2];
__device__ uint32_t g_Vtlo[B][DV][LKV / 2];
__device__ uint32_t g_Ehi[B][LQ][LKV / 2];
__device__ uint32_t g_Elo[B][LQ][LKV / 2];
__device__ float    g_partial[B][LKV / 128][LQ];
__device__ float    g_partC[KSPLIT][B][LQ][DV];

// ---------------------------------------------------------------------------
// Helpers
// ---------------------------------------------------------------------------
__device__ __forceinline__ void cvt_split(float x0, float x1,
                                          uint32_t& hi, uint32_t& lo) {
    asm("cvt.rn.bf16x2.f32 %0, %1, %2;" : "=r"(hi) : "f"(x1), "f"(x0));
    float f0 = __uint_as_float(hi << 16);
    float f1 = __uint_as_float(hi & 0xffff0000u);
    asm("cvt.rn.bf16x2.f32 %0, %1, %2;" : "=r"(lo) : "f"(x1 - f1), "f"(x0 - f0));
}

__device__ __forceinline__ void mma16816(float* c,
                                         uint32_t a0, uint32_t a1, uint32_t a2, uint32_t a3,
                                         uint32_t b0, uint32_t b1) {
    asm volatile(
        "mma.sync.aligned.m16n8k16.row.col.f32.bf16.bf16.f32 "
        "{%0,%1,%2,%3}, {%4,%5,%6,%7}, {%8,%9}, {%0,%1,%2,%3};"
        : "+f"(c[0]), "+f"(c[1]), "+f"(c[2]), "+f"(c[3])
        : "r"(a0), "r"(a1), "r"(a2), "r"(a3), "r"(b0), "r"(b1));
}

__device__ __forceinline__ void ldsm_x4(uint32_t& r0, uint32_t& r1,
                                        uint32_t& r2, uint32_t& r3, uint32_t addr) {
    asm volatile("ldmatrix.sync.aligned.m8n8.x4.shared.b16 {%0,%1,%2,%3}, [%4];"
                 : "=r"(r0), "=r"(r1), "=r"(r2), "=r"(r3) : "r"(addr));
}

__device__ __forceinline__ void ldsm_x2(uint32_t& r0, uint32_t& r1, uint32_t addr) {
    asm volatile("ldmatrix.sync.aligned.m8n8.x2.shared.b16 {%0,%1}, [%2];"
                 : "=r"(r0), "=r"(r1) : "r"(addr));
}

__device__ __forceinline__ void cp16(uint32_t dst, const void* src) {
    asm volatile("cp.async.cg.shared.global [%0], [%1], 16;" :: "r"(dst), "l"(src));
}
#define CP_COMMIT() asm volatile("cp.async.commit_group;" ::: "memory")
#define CP_WAIT0()  asm volatile("cp.async.wait_group 0;" ::: "memory")
#define CP_WAIT1()  asm volatile("cp.async.wait_group 1;" ::: "memory")

// ---------------------------------------------------------------------------
// Convert kernels: fp32 -> split bf16 planes
// ---------------------------------------------------------------------------
__global__ void __launch_bounds__(256)
convert_qk_kernel(const float* __restrict__ Q, const float* __restrict__ K) {
    int idx = blockIdx.x * 256 + threadIdx.x;
    const float4* src = (const float4*)(blockIdx.y ? K : Q);
    uint2* dhi = (uint2*)(blockIdx.y ? &g_Khi[0][0][0] : &g_Qhi[0][0][0]);
    uint2* dlo = (uint2*)(blockIdx.y ? &g_Klo[0][0][0] : &g_Qlo[0][0][0]);
    float4 v = src[idx];
    uint32_t h0, l0, h1, l1;
    cvt_split(v.x, v.y, h0, l0);
    cvt_split(v.z, v.w, h1, l1);
    dhi[idx] = make_uint2(h0, h1);
    dlo[idx] = make_uint2(l0, l1);
}

__global__ void __launch_bounds__(256)
convert_v_kernel(const float* __restrict__ V) {
    __shared__ float Vs[32][132];
    const int b  = blockIdx.y;
    const int k0 = blockIdx.x * 32;
    const int tid = threadIdx.x;
#pragma unroll
    for (int l = 0; l < 4; l++) {
        int idx = tid + l * 256;
        int r  = idx >> 5;
        int c4 = idx & 31;
        float4 v = *(const float4*)&V[((size_t)(b * LKV + k0 + r)) * DV + c4 * 4];
        Vs[r][c4 * 4 + 0] = v.x; Vs[r][c4 * 4 + 1] = v.y;
        Vs[r][c4 * 4 + 2] = v.z; Vs[r][c4 * 4 + 3] = v.w;
    }
    __syncthreads();
#pragma unroll
    for (int l = 0; l < 8; l++) {
        int idx = tid + l * 256;
        int n   = idx >> 4;
        int kpl = idx & 15;
        float v0 = Vs[2 * kpl][n];
        float v1 = Vs[2 * kpl + 1][n];
        uint32_t h, lo;
        cvt_split(v0, v1, h, lo);
        g_Vthi[b][n][k0 / 2 + kpl] = h;
        g_Vtlo[b][n][k0 / 2 + kpl] = lo;
    }
}

// ---------------------------------------------------------------------------
// Kernel 1: scores -> exp(s) split planes + per-row partial exp-sums.
// Block tile 128x128. Double-buffered cp.async pipeline, 4 chunks of 32 k.
// Stage layout: rows stride 20 u32 (80 B, 16B-aligned, conflict-free ldsm).
// ---------------------------------------------------------------------------
#define QK_STAGE_B 40960   // 4 planes * 128 rows * 20 u32 * 4 B
#define QK_QLO 10240
#define QK_KHI 20480
#define QK_KLO 30720

__global__ void __launch_bounds__(256, 2)
qk_mma_kernel() {
    extern __shared__ uint32_t sm[];
    const uint32_t smemS = (uint32_t)__cvta_generic_to_shared(sm);

    const int b = blockIdx.z;
    const int mBase = blockIdx.y * 128;
    const int nBase = blockIdx.x * 128;

    const int tid  = threadIdx.x;
    const int lane = tid & 31;
    const int warp = tid >> 5;
    const int g    = lane >> 2;
    const int tig  = lane & 3;
    const int wm   = warp >> 2;
    const int wn   = warp & 3;

    const uint32_t aBase = ((wm * 64 + (lane & 7) + (lane & 8)) * 20
                            + ((lane >> 4) & 1) * 4) * 4;
    const uint32_t bBase = ((wn * 32 + (lane & 7)) * 20
                            + ((lane >> 3) & 1) * 4) * 4;

    float acc[4][4][4];
#pragma unroll
    for (int mt = 0; mt < 4; mt++)
#pragma unroll
        for (int nt = 0; nt < 4; nt++)
#pragma unroll
            for (int i = 0; i < 4; i++) acc[mt][nt][i] = 0.0f;

    // fill chunk c (32 k-elems = 16 u32) into stage s
    auto fill = [&](int c, int s) {
#pragma unroll
        for (int l = 0; l < 2; l++) {
            int idx = tid + l * 256;      // 0..511
            int row = idx >> 2;
            int cc  = idx & 3;
            uint32_t d = smemS + (uint32_t)s * QK_STAGE_B + row * 80 + cc * 16;
            int kc = c * 16 + cc * 4;
            cp16(d,          &g_Qhi[b][mBase + row][kc]);
            cp16(d + QK_QLO, &g_Qlo[b][mBase + row][kc]);
            cp16(d + QK_KHI, &g_Khi[b][nBase + row][kc]);
            cp16(d + QK_KLO, &g_Klo[b][nBase + row][kc]);
        }
        CP_COMMIT();
    };

    fill(0, 0);
#pragma unroll
    for (int c = 0; c < 4; c++) {
        if (c < 3) { fill(c + 1, (c + 1) & 1); CP_WAIT1(); }
        else       { CP_WAIT0(); }
        __syncthreads();

        const uint32_t stg = smemS + (uint32_t)(c & 1) * QK_STAGE_B;
#pragma unroll
        for (int ks = 0; ks < 2; ks++) {
            uint32_t Ah[4][4], Al[4][4];
#pragma unroll
            for (int mt = 0; mt < 4; mt++) {
                uint32_t a = stg + aBase + (uint32_t)mt * 1280 + (uint32_t)ks * 32;
                ldsm_x4(Ah[mt][0], Ah[mt][1], Ah[mt][2], Ah[mt][3], a);
                ldsm_x4(Al[mt][0], Al[mt][1], Al[mt][2], Al[mt][3], a + QK_QLO);
            }
#pragma unroll
            for (int nt = 0; nt < 4; nt++) {
                uint32_t ba = stg + QK_KHI + bBase + (uint32_t)nt * 640 + (uint32_t)ks * 32;
                uint32_t bh0, bh1, bl0, bl1;
                ldsm_x2(bh0, bh1, ba);
                ldsm_x2(bl0, bl1, ba + QK_QLO);   // KLO = KHI + 10240
#pragma unroll
                for (int mt = 0; mt < 4; mt++) {
                    mma16816(acc[mt][nt], Ah[mt][0], Ah[mt][1], Ah[mt][2], Ah[mt][3], bh0, bh1);
                    mma16816(acc[mt][nt], Ah[mt][0], Ah[mt][1], Ah[mt][2], Ah[mt][3], bl0, bl1);
                    mma16816(acc[mt][nt], Al[mt][0], Al[mt][1], Al[mt][2], Al[mt][3], bh0, bh1);
                }
            }
        }
        __syncthreads();
    }

    // ---- epilogue: e = exp(s*scale); write split E planes + partial sums ----
    const float scale = 0.08838834764831845f;  // 1/sqrt(128)
    float* part = (float*)sm;
#pragma unroll
    for (int mt = 0; mt < 4; mt++) {
        int m0 = mBase + wm * 64 + mt * 16 + g;
        float eA = 0.0f, eB = 0.0f;
#pragma unroll
        for (int nt = 0; nt < 4; nt++) {
            int kp = (nBase >> 1) + wn * 16 + nt * 4 + tig;
            float e0 = __expf(acc[mt][nt][0] * scale);
            float e1 = __expf(acc[mt][nt][1] * scale);
            float e2 = __expf(acc[mt][nt][2] * scale);
            float e3 = __expf(acc[mt][nt][3] * scale);
            uint32_t h, lo;
            cvt_split(e0, e1, h, lo);
            g_Ehi[b][m0][kp] = h;
            g_Elo[b][m0][kp] = lo;
            cvt_split(e2, e3, h, lo);
            g_Ehi[b][m0 + 8][kp] = h;
            g_Elo[b][m0 + 8][kp] = lo;
            eA += e0 + e1;
            eB += e2 + e3;
        }
        eA += __shfl_xor_sync(0xffffffffu, eA, 1);
        eA += __shfl_xor_sync(0xffffffffu, eA, 2);
        eB += __shfl_xor_sync(0xffffffffu, eB, 1);
        eB += __shfl_xor_sync(0xffffffffu, eB, 2);
        if (tig == 0) {
            part[wn * 128 + wm * 64 + mt * 16 + g]     = eA;
            part[wn * 128 + wm * 64 + mt * 16 + g + 8] = eB;
        }
    }
    __syncthreads();
    if (tid < 128) {
        float s = part[tid] + part[128 + tid] + part[256 + tid] + part[384 + tid];
        g_partial[b][blockIdx.x][mBase + tid] = s;
    }
}

// ---------------------------------------------------------------------------
// Kernel 2 (fused, split-K): weights output + partial C = E @ V (scaled).
// Block tile 64(M) x 128(N=DV), K range 512, 8 chunks of 64, double-buffered.
// Stage (u32): Whi 0, Wlo 2304, Vhi 4608, Vlo 9216; stage size 13824 u32.
// ---------------------------------------------------------------------------
#define WV_ROW 36
#define WV_STAGE_U32 13824
#define WV_STAGE_B   55296
#define WV_WLO_B  9216
#define WV_VHI_B 18432

__global__ void __launch_bounds__(256, 2)
wv_fused_kernel(float* __restrict__ Wgt) {
    extern __shared__ uint32_t sm[];
    const uint32_t smemS = (uint32_t)__cvta_generic_to_shared(sm);
    float* invs = (float*)(sm + 2 * WV_STAGE_U32);   // 64 floats

    const int b = blockIdx.z;
    const int ksp = blockIdx.y;
    const int mBase = blockIdx.x * 64;
    const int kBase = ksp * KRANGE;

    const int tid  = threadIdx.x;
    const int lane = tid & 31;
    const int warp = tid >> 5;
    const int g    = lane >> 2;
    const int tig  = lane & 3;
    const int wm   = warp >> 2;
    const int wn   = warp & 3;

    const uint32_t aBase = ((wm * 32 + (lane & 7) + (lane & 8)) * WV_ROW
                            + ((lane >> 4) & 1) * 4) * 4;

    // ---- row inverse sums from partials ----
    if (tid < 64) {
        float s = 0.0f;
#pragma unroll
        for (int nb = 0; nb < LKV / 128; nb++) s += g_partial[b][nb][mBase + tid];
        invs[tid] = 1.0f / s;
    }

    float acc[2][4][4];
#pragma unroll
    for (int mt = 0; mt < 2; mt++)
#pragma unroll
        for (int nt = 0; nt < 4; nt++)
#pragma unroll
            for (int i = 0; i < 4; i++) acc[mt][nt][i] = 0.0f;

    auto fill = [&](int ch, int s) {
        const int kp0 = (kBase + ch * 64) >> 1;
        const uint32_t base = smemS + (uint32_t)s * WV_STAGE_B;
#pragma unroll
        for (int l = 0; l < 2; l++) {
            int idx = tid + l * 256;      // 0..511
            int row = idx >> 3;
            int c   = idx & 7;
            uint32_t d = base + row * 144 + c * 16;
            cp16(d,            &g_Ehi[b][mBase + row][kp0 + c * 4]);
            cp16(d + WV_WLO_B, &g_Elo[b][mBase + row][kp0 + c * 4]);
        }
#pragma unroll
        for (int l = 0; l < 4; l++) {
            int idx = tid + l * 256;      // 0..1023
            int n = idx >> 3;
            int c = idx & 7;
            uint32_t d = base + WV_VHI_B + n * 144 + c * 16;
            cp16(d,            &g_Vthi[b][n][kp0 + c * 4]);
            cp16(d + WV_VHI_B, &g_Vtlo[b][n][kp0 + c * 4]);
        }
        CP_COMMIT();
    };

    fill(0, 0);
    __syncthreads();     // also covers invs visibility

    for (int ch = 0; ch < KRANGE / 64; ch++) {
        if (ch < KRANGE / 64 - 1) { fill(ch + 1, (ch + 1) & 1); CP_WAIT1(); }
        else                      { CP_WAIT0(); }
        __syncthreads();

        const int s = ch & 1;
        const uint32_t stgB = smemS + (uint32_t)s * WV_STAGE_B;
        uint32_t* st = sm + s * WV_STAGE_U32;
        const int k0 = kBase + ch * 64;

        // ---- weights output: P = (Ehi + Elo) * inv ----
#pragma unroll
        for (int l = 0; l < 4; l++) {
            int idx = tid + l * 256;      // 0..1023
            int row = idx >> 4;           // 0..63
            int c4  = idx & 15;
            uint2 h  = *(uint2*)&st[row * WV_ROW + c4 * 2];
            uint2 lo = *(uint2*)&st[2304 + row * WV_ROW + c4 * 2];
            float inv = invs[row];
            float4 o;
            o.x = (__uint_as_float(h.x << 16)         + __uint_as_float(lo.x << 16))         * inv;
            o.y = (__uint_as_float(h.x & 0xffff0000u) + __uint_as_float(lo.x & 0xffff0000u)) * inv;
            o.z = (__uint_as_float(h.y << 16)         + __uint_as_float(lo.y << 16))         * inv;
            o.w = (__uint_as_float(h.y & 0xffff0000u) + __uint_as_float(lo.y & 0xffff0000u)) * inv;
            *(float4*)&Wgt[(size_t)b * LQ * LKV + (size_t)(mBase + row) * LKV + k0 + c4 * 4] = o;
        }

        // ---- mma: 4 k16 steps ----
#pragma unroll
        for (int ks = 0; ks < 4; ks++) {
            const int kp = ks * 8;
            uint32_t Ah[2][4], Al[2][4];
#pragma unroll
            for (int mt = 0; mt < 2; mt++) {
                uint32_t a = stgB + aBase + (uint32_t)mt * (16 * WV_ROW * 4) + (uint32_t)ks * 32;
                ldsm_x4(Ah[mt][0], Ah[mt][1], Ah[mt][2], Ah[mt][3], a);
                ldsm_x4(Al[mt][0], Al[mt][1], Al[mt][2], Al[mt][3], a + WV_WLO_B);
            }
#pragma unroll
            for (int nt = 0; nt < 4; nt++) {
                int rb = (wn * 32 + nt * 8 + g) * WV_ROW + kp + tig;
                uint32_t bh0 = st[4608 + rb], bh1 = st[4608 + rb + 4];
                uint32_t bl0 = st[9216 + rb], bl1 = st[9216 + rb + 4];
#pragma unroll
                for (int mt = 0; mt < 2; mt++) {
                    mma16816(acc[mt][nt], Ah[mt][0], Ah[mt][1], Ah[mt][2], Ah[mt][3], bh0, bh1);
                    mma16816(acc[mt][nt], Ah[mt][0], Ah[mt][1], Ah[mt][2], Ah[mt][3], bl0, bl1);
                    mma16816(acc[mt][nt], Al[mt][0], Al[mt][1], Al[mt][2], Al[mt][3], bh0, bh1);
                }
            }
        }
        __syncthreads();
    }

    float* Cp = &g_partC[ksp][b][mBase][0];
#pragma unroll
    for (int mt = 0; mt < 2; mt++) {
        int r = wm * 32 + mt * 16 + g;
        float ia = invs[r];
        float ib = invs[r + 8];
#pragma unroll
        for (int nt = 0; nt < 4; nt++) {
            int n0 = wn * 32 + nt * 8 + tig * 2;
            float2 v0 = make_float2(acc[mt][nt][0] * ia, acc[mt][nt][1] * ia);
            float2 v1 = make_float2(acc[mt][nt][2] * ib, acc[mt][nt][3] * ib);
            *(float2*)&Cp[(size_t)r * DV + n0]       = v0;
            *(float2*)&Cp[(size_t)(r + 8) * DV + n0] = v1;
        }
    }
}

// ---------------------------------------------------------------------------
// Kernel 3: reduce the KSPLIT partial C buffers into the context output.
// ---------------------------------------------------------------------------
__global__ void __launch_bounds__(256) reduce_kernel(float* __restrict__ C) {
    size_t i4 = (size_t)blockIdx.x * 256 + threadIdx.x;
    const float4* p0 = (const float4*)&g_partC[0][0][0][0];
    const float4* p1 = (const float4*)&g_partC[1][0][0][0];
    const float4* p2 = (const float4*)&g_partC[2][0][0][0];
    const float4* p3 = (const float4*)&g_partC[3][0][0][0];
    float4 a = p0[i4], b4 = p1[i4], c = p2[i4], d = p3[i4];
    float4 o;
    o.x = (a.x + b4.x) + (c.x + d.x);
    o.y = (a.y + b4.y) + (c.y + d.y);
    o.z = (a.z + b4.z) + (c.z + d.z);
    o.w = (a.w + b4.w) + (c.w + d.w);
    ((float4*)C)[i4] = o;
}

// ---------------------------------------------------------------------------
extern "C" void kernel_launch(void* const* d_in, const int* in_sizes, int n_in,
                              void* d_out, int out_size) {
    const float* Q = (const float*)d_in[0];
    const float* K = (const float*)d_in[1];
    const float* V = (const float*)d_in[2];

    float* Wgt = (float*)d_out;                        // weights (B,LQ,LKV)
    float* Ctx = (float*)d_out + (size_t)B * LQ * LKV; // context (B,LQ,DV)

    const int qk_smem = 2 * QK_STAGE_B;                // 81920 B
    const int wv_smem = 2 * WV_STAGE_B + 256;          // 110848 B
    cudaFuncSetAttribute(qk_mma_kernel, cudaFuncAttributeMaxDynamicSharedMemorySize, qk_smem);
    cudaFuncSetAttribute(wv_fused_kernel, cudaFuncAttributeMaxDynamicSharedMemorySize, wv_smem);

    dim3 gc(B * LQ * D / 4 / 256, 2);
    convert_qk_kernel<<<gc, 256>>>(Q, K);
    dim3 gv(LKV / 32, B);
    convert_v_kernel<<<gv, 256>>>(V);

    dim3 g1(LKV / 128, LQ / 128, B);
    qk_mma_kernel<<<g1, 256, qk_smem>>>();

    dim3 g2(LQ / 64, KSPLIT, B);
    wv_fused_kernel<<<g2, 256, wv_smem>>>(Wgt);

    const int nC4 = B * LQ * DV / 4;
    reduce_kernel<<<nC4 / 256, 256>>>(Ctx);
}